// round 2
// baseline (speedup 1.0000x reference)
#include <cuda_runtime.h>
#include <math.h>

#define Bsz   4
#define Sq    2048
#define Dm    2048
#define Hh    16
#define HDim  128
#define Mrows (Bsz*Sq)      /* 8192 */
#define QKVN  (3*Dm)        /* 6144 */

// ---------------- scratch (device globals; no allocation allowed) ----------
__device__ float g_x[(size_t)Mrows * Dm];      // layernorm output
__device__ float g_qkv[(size_t)Mrows * QKVN];  // qkv projection
__device__ float g_att[(size_t)Mrows * Dm];    // merged-head attention out

// ---------------- packed f32x2 helpers (sm_100+ PTX) -----------------------
__device__ __forceinline__ unsigned long long pk2(float lo, float hi) {
    unsigned long long r;
    asm("mov.b64 %0, {%1, %2};"
        : "=l"(r) : "r"(__float_as_uint(lo)), "r"(__float_as_uint(hi)));
    return r;
}
__device__ __forceinline__ float2 up2(unsigned long long v) {
    unsigned int lo, hi;
    asm("mov.b64 {%0, %1}, %2;" : "=r"(lo), "=r"(hi) : "l"(v));
    return make_float2(__uint_as_float(lo), __uint_as_float(hi));
}
__device__ __forceinline__ void fma2(unsigned long long& c,
                                     unsigned long long a, unsigned long long b) {
    asm("fma.rn.f32x2 %0, %1, %2, %0;" : "+l"(c) : "l"(a), "l"(b));
}
__device__ __forceinline__ void mul2(unsigned long long& c, unsigned long long a) {
    asm("mul.rn.f32x2 %0, %0, %1;" : "+l"(c) : "l"(a));
}

// ---------------- LayerNorm: one block per row -----------------------------
__global__ void __launch_bounds__(256) ln_kernel(
    const float* __restrict__ x, const float* __restrict__ gamma,
    const float* __restrict__ beta, float* __restrict__ y)
{
    const int row = blockIdx.x, t = threadIdx.x;
    const float4* xr = (const float4*)(x + (size_t)row * Dm);
    float4 v0 = xr[t], v1 = xr[t + 256];
    float s  = v0.x + v0.y + v0.z + v0.w + v1.x + v1.y + v1.z + v1.w;
    float ss = v0.x*v0.x + v0.y*v0.y + v0.z*v0.z + v0.w*v0.w
             + v1.x*v1.x + v1.y*v1.y + v1.z*v1.z + v1.w*v1.w;
    #pragma unroll
    for (int o = 16; o; o >>= 1) {
        s  += __shfl_xor_sync(0xffffffffu, s,  o);
        ss += __shfl_xor_sync(0xffffffffu, ss, o);
    }
    __shared__ float sh[16];
    const int w = t >> 5;
    if ((t & 31) == 0) { sh[w] = s; sh[8 + w] = ss; }
    __syncthreads();
    s = 0.f; ss = 0.f;
    #pragma unroll
    for (int i = 0; i < 8; i++) { s += sh[i]; ss += sh[8 + i]; }
    const float mean = s * (1.0f / Dm);
    const float var  = ss * (1.0f / Dm) - mean * mean;
    const float rstd = rsqrtf(var + 1e-5f);

    const float4* g4 = (const float4*)gamma;
    const float4* b4 = (const float4*)beta;
    float4 G0 = g4[t], G1 = g4[t + 256], B0 = b4[t], B1 = b4[t + 256];
    float4 o0, o1;
    o0.x = (v0.x - mean) * rstd * G0.x + B0.x;
    o0.y = (v0.y - mean) * rstd * G0.y + B0.y;
    o0.z = (v0.z - mean) * rstd * G0.z + B0.z;
    o0.w = (v0.w - mean) * rstd * G0.w + B0.w;
    o1.x = (v1.x - mean) * rstd * G1.x + B1.x;
    o1.y = (v1.y - mean) * rstd * G1.y + B1.y;
    o1.z = (v1.z - mean) * rstd * G1.z + B1.z;
    o1.w = (v1.w - mean) * rstd * G1.w + B1.w;
    float4* yr = (float4*)(y + (size_t)row * Dm);
    yr[t] = o0; yr[t + 256] = o1;
}

// ---------------- SGEMM (f32x2 packed): C = A[MxK] * B[KxN] + bias ---------
// BM=BN=128, BK=8, 256 threads, 8x8 micro-tile (8x4 f32x2 pairs).
__global__ void __launch_bounds__(256, 2) sgemm_bias_kernel(
    const float* __restrict__ A, const float* __restrict__ Bm,
    const float* __restrict__ bias, float* __restrict__ C,
    int M, int N, int K)
{
    __shared__ float As[8][128];
    __shared__ float Bs[8][128];
    const int tid = threadIdx.x;
    const int m0 = blockIdx.y * 128, n0 = blockIdx.x * 128;
    const int arow = tid >> 1, acol = (tid & 1) * 4;
    const int brow = tid >> 5, bcol = (tid & 31) * 4;
    const float* Ap = A + (size_t)(m0 + arow) * K + acol;
    const float* Bp = Bm + (size_t)brow * N + n0 + bcol;
    float4 aR = *(const float4*)Ap;
    float4 bR = *(const float4*)Bp;
    const int tx = tid & 15, ty = tid >> 4;

    unsigned long long acc[8][4];
    #pragma unroll
    for (int i = 0; i < 8; i++)
        #pragma unroll
        for (int j = 0; j < 4; j++) acc[i][j] = 0ULL;

    const int KT = K >> 3;
    for (int kt = 0; kt < KT; ++kt) {
        __syncthreads();
        As[acol + 0][arow] = aR.x;
        As[acol + 1][arow] = aR.y;
        As[acol + 2][arow] = aR.z;
        As[acol + 3][arow] = aR.w;
        *(float4*)&Bs[brow][bcol] = bR;
        __syncthreads();
        if (kt + 1 < KT) {
            aR = *(const float4*)(Ap + (size_t)(kt + 1) * 8);
            bR = *(const float4*)(Bp + (size_t)(kt + 1) * 8 * N);
        }
        #pragma unroll
        for (int k = 0; k < 8; k++) {
            unsigned long long pa[8], pb[4];
            #pragma unroll
            for (int i = 0; i < 8; i++) {
                float av = As[k][ty * 8 + i];
                pa[i] = pk2(av, av);
            }
            #pragma unroll
            for (int j = 0; j < 4; j++)
                pb[j] = *(const unsigned long long*)&Bs[k][tx * 8 + 2 * j];
            #pragma unroll
            for (int i = 0; i < 8; i++)
                #pragma unroll
                for (int j = 0; j < 4; j++) fma2(acc[i][j], pa[i], pb[j]);
        }
    }

    #pragma unroll
    for (int i = 0; i < 8; i++) {
        const size_t row = (size_t)(m0 + ty * 8 + i);
        float* Cp = C + row * N + n0 + tx * 8;
        const float* bp = bias + n0 + tx * 8;
        #pragma unroll
        for (int j = 0; j < 4; j++) {
            float2 f = up2(acc[i][j]);
            *(float2*)&Cp[2 * j] = make_float2(f.x + bp[2 * j], f.y + bp[2 * j + 1]);
        }
    }
}

// ---------------- Flash attention (causal, fp32, f32x2 inner loops) --------
// Tile 64(q) x 64(k), hd=128. 256 threads: ty=tid/16 -> 4 q rows,
// tx=tid%16 -> score k cols {j*16+tx}, O d cols {j*32 + tx*2}.
#define LDT 130   /* row stride; 130 % 32 == 2 -> conflict-free lane-stride-1/2 reads */

__global__ void __launch_bounds__(256, 1) flash_kernel(
    const float* __restrict__ qkv, float* __restrict__ out)
{
    extern __shared__ float sm[];
    float* Qs = sm;                 // 64 * LDT
    float* Ks = Qs + 64 * LDT;
    float* Vs = Ks + 64 * LDT;
    float* Ps = Vs + 64 * LDT;      // 64 * 64

    const int b = blockIdx.z, h = blockIdx.y, qt = blockIdx.x;
    const int tid = threadIdx.x, tx = tid & 15, ty = tid >> 4;
    const float scale = 0.08838834764831845f;  // 1/sqrt(128)

    // load Q tile
    const float* qbase = qkv + ((size_t)(b * Sq + qt * 64)) * QKVN + h * HDim;
    for (int i = tid; i < 64 * 64; i += 256) {
        int r = i >> 6, c = (i & 63) * 2;
        *(float2*)&Qs[r * LDT + c] = *(const float2*)(qbase + (size_t)r * QKVN + c);
    }

    float m_i[4], l_i[4];
    unsigned long long o[4][4];
    #pragma unroll
    for (int i = 0; i < 4; i++) {
        m_i[i] = -1e30f; l_i[i] = 0.f;
        #pragma unroll
        for (int j = 0; j < 4; j++) o[i][j] = 0ULL;
    }

    for (int kt = 0; kt <= qt; ++kt) {
        __syncthreads();   // prev PV reads of Vs/Ps done
        const float* kbase = qkv + ((size_t)(b * Sq + kt * 64)) * QKVN + Dm + h * HDim;
        const float* vbase = kbase + Dm;
        for (int i = tid; i < 64 * 64; i += 256) {
            int r = i >> 6, c = (i & 63) * 2;
            *(float2*)&Ks[r * LDT + c] = *(const float2*)(kbase + (size_t)r * QKVN + c);
            *(float2*)&Vs[r * LDT + c] = *(const float2*)(vbase + (size_t)r * QKVN + c);
        }
        __syncthreads();

        // scores: packed dot over d
        unsigned long long sacc[4][4];
        #pragma unroll
        for (int i = 0; i < 4; i++)
            #pragma unroll
            for (int j = 0; j < 4; j++) sacc[i][j] = 0ULL;
        #pragma unroll 2
        for (int d2 = 0; d2 < 64; ++d2) {
            unsigned long long qa[4], kb[4];
            #pragma unroll
            for (int i = 0; i < 4; i++)
                qa[i] = *(const unsigned long long*)&Qs[(ty * 4 + i) * LDT + 2 * d2];
            #pragma unroll
            for (int j = 0; j < 4; j++)
                kb[j] = *(const unsigned long long*)&Ks[(j * 16 + tx) * LDT + 2 * d2];
            #pragma unroll
            for (int i = 0; i < 4; i++)
                #pragma unroll
                for (int j = 0; j < 4; j++) fma2(sacc[i][j], qa[i], kb[j]);
        }

        float s[4][4];
        #pragma unroll
        for (int i = 0; i < 4; i++)
            #pragma unroll
            for (int j = 0; j < 4; j++) {
                float2 f = up2(sacc[i][j]);
                s[i][j] = (f.x + f.y) * scale;
            }
        if (kt == qt) {
            #pragma unroll
            for (int i = 0; i < 4; i++)
                #pragma unroll
                for (int j = 0; j < 4; j++)
                    if (j * 16 + tx > ty * 4 + i) s[i][j] = -1e30f;
        }

        // online softmax
        #pragma unroll
        for (int i = 0; i < 4; i++) {
            float rm = fmaxf(fmaxf(s[i][0], s[i][1]), fmaxf(s[i][2], s[i][3]));
            #pragma unroll
            for (int off = 8; off; off >>= 1)
                rm = fmaxf(rm, __shfl_xor_sync(0xffffffffu, rm, off));
            const float nm = fmaxf(m_i[i], rm);
            const float corr = __expf(m_i[i] - nm);
            m_i[i] = nm;
            float rs = 0.f;
            #pragma unroll
            for (int j = 0; j < 4; j++) {
                float p = __expf(s[i][j] - nm);
                Ps[(ty * 4 + i) * 64 + j * 16 + tx] = p;
                rs += p;
            }
            #pragma unroll
            for (int off = 8; off; off >>= 1)
                rs += __shfl_xor_sync(0xffffffffu, rs, off);
            l_i[i] = l_i[i] * corr + rs;
            unsigned long long c2 = pk2(corr, corr);
            #pragma unroll
            for (int j = 0; j < 4; j++) mul2(o[i][j], c2);
        }
        __syncthreads();   // Ps visible

        // O += P * V
        #pragma unroll 2
        for (int k = 0; k < 64; ++k) {
            unsigned long long pp[4], vv[4];
            #pragma unroll
            for (int i = 0; i < 4; i++) {
                float pf = Ps[(ty * 4 + i) * 64 + k];
                pp[i] = pk2(pf, pf);
            }
            #pragma unroll
            for (int j = 0; j < 4; j++)
                vv[j] = *(const unsigned long long*)&Vs[k * LDT + j * 32 + tx * 2];
            #pragma unroll
            for (int i = 0; i < 4; i++)
                #pragma unroll
                for (int j = 0; j < 4; j++) fma2(o[i][j], pp[i], vv[j]);
        }
    }

    // epilogue: normalize, write merged-head layout [B,S,H*HD]
    #pragma unroll
    for (int i = 0; i < 4; i++) {
        const float inv = 1.0f / l_i[i];
        const int srow = b * Sq + qt * 64 + ty * 4 + i;
        float* op = out + (size_t)srow * Dm + h * HDim;
        #pragma unroll
        for (int j = 0; j < 4; j++) {
            float2 f = up2(o[i][j]);
            *(float2*)&op[j * 32 + tx * 2] = make_float2(f.x * inv, f.y * inv);
        }
    }
}

// ---------------- launch ----------------------------------------------------
extern "C" void kernel_launch(void* const* d_in, const int* in_sizes, int n_in,
                              void* d_out, int out_size)
{
    const float* hs    = (const float*)d_in[0];
    const float* gamma = (const float*)d_in[1];
    const float* beta  = (const float*)d_in[2];
    const float* Wqkv  = (const float*)d_in[3];
    const float* bqkv  = (const float*)d_in[4];
    const float* Wproj = (const float*)d_in[5];
    const float* bproj = (const float*)d_in[6];
    float* out = (float*)d_out;

    void *px, *pq, *pa;
    cudaGetSymbolAddress(&px, g_x);
    cudaGetSymbolAddress(&pq, g_qkv);
    cudaGetSymbolAddress(&pa, g_att);
    float* xn  = (float*)px;
    float* qkv = (float*)pq;
    float* att = (float*)pa;

    ln_kernel<<<Mrows, 256>>>(hs, gamma, beta, xn);

    dim3 g1(QKVN / 128, Mrows / 128);
    sgemm_bias_kernel<<<g1, 256>>>(xn, Wqkv, bqkv, qkv, Mrows, QKVN, Dm);

    const int FLASH_SMEM = (3 * 64 * LDT + 64 * 64) * 4;  // 116,224 B
    cudaFuncSetAttribute(flash_kernel,
                         cudaFuncAttributeMaxDynamicSharedMemorySize, FLASH_SMEM);
    flash_kernel<<<dim3(Sq / 64, Hh, Bsz), 256, FLASH_SMEM>>>(qkv, att);

    dim3 g2(Dm / 128, Mrows / 128);
    sgemm_bias_kernel<<<g2, 256>>>(att, Wproj, bproj, out, Mrows, Dm, Dm);
}

// round 7
// speedup vs baseline: 1.8246x; 1.8246x over previous
#include <cuda_runtime.h>
#include <cuda_fp16.h>
#include <math.h>
#include <stdint.h>

#define Bsz   4
#define Sq    2048
#define Dm    2048
#define Hh    16
#define HDim  128
#define Mrows (Bsz*Sq)      /* 8192 */
#define QKVN  (3*Dm)        /* 6144 */

// ---------------- scratch (device globals; no allocation allowed) ----------
__device__ float g_qkv[(size_t)Mrows * QKVN];   // qkv projection (f32)
__device__ __half g_xh[(size_t)Mrows * Dm];     // LN out hi/lo (fp16 split)
__device__ __half g_xl[(size_t)Mrows * Dm];
__device__ __half g_ah[(size_t)Mrows * Dm];     // attn out hi/lo
__device__ __half g_al[(size_t)Mrows * Dm];
__device__ __half g_wqh[(size_t)QKVN * Dm];     // W_qkv^T hi/lo
__device__ __half g_wql[(size_t)QKVN * Dm];
__device__ __half g_wph[(size_t)Dm * Dm];       // W_proj^T hi/lo
__device__ __half g_wpl[(size_t)Dm * Dm];

// ---------------- small helpers --------------------------------------------
__device__ __forceinline__ void hsplit(float x, __half& h, __half& l) {
    h = __float2half_rn(x);
    l = __float2half_rn(x - __half2float(h));
}

// packed f32x2 helpers (flash kernel)
__device__ __forceinline__ unsigned long long pk2(float lo, float hi) {
    unsigned long long r;
    asm("mov.b64 %0, {%1, %2};"
        : "=l"(r) : "r"(__float_as_uint(lo)), "r"(__float_as_uint(hi)));
    return r;
}
__device__ __forceinline__ float2 up2(unsigned long long v) {
    unsigned int lo, hi;
    asm("mov.b64 {%0, %1}, %2;" : "=r"(lo), "=r"(hi) : "l"(v));
    return make_float2(__uint_as_float(lo), __uint_as_float(hi));
}
__device__ __forceinline__ void fma2(unsigned long long& c,
                                     unsigned long long a, unsigned long long b) {
    asm("fma.rn.f32x2 %0, %1, %2, %0;" : "+l"(c) : "l"(a), "l"(b));
}
__device__ __forceinline__ void mul2(unsigned long long& c, unsigned long long a) {
    asm("mul.rn.f32x2 %0, %0, %1;" : "+l"(c) : "l"(a));
}

// ---------------- Ampere-era primitives (valid on plain sm_103 target) -----
__device__ __forceinline__ uint32_t cvta_smem(const void* p) {
    return (uint32_t)__cvta_generic_to_shared(p);
}
__device__ __forceinline__ void cp16(uint32_t s, const void* g) {
    asm volatile("cp.async.cg.shared.global [%0], [%1], 16;" :: "r"(s), "l"(g));
}
__device__ __forceinline__ void cp_commit() {
    asm volatile("cp.async.commit_group;" ::: "memory");
}
template<int W> __device__ __forceinline__ void cp_wait() {
    asm volatile("cp.async.wait_group %0;" :: "n"(W) : "memory");
}
__device__ __forceinline__ void ldsm4(uint32_t* r, uint32_t addr) {
    asm volatile("ldmatrix.sync.aligned.m8n8.x4.shared.b16 {%0,%1,%2,%3}, [%4];"
                 : "=r"(r[0]), "=r"(r[1]), "=r"(r[2]), "=r"(r[3]) : "r"(addr));
}
__device__ __forceinline__ void mma16816(float* c, const uint32_t* a, const uint32_t* b) {
    asm volatile("mma.sync.aligned.m16n8k16.row.col.f32.f16.f16.f32 "
                 "{%0,%1,%2,%3}, {%4,%5,%6,%7}, {%8,%9}, {%0,%1,%2,%3};"
                 : "+f"(c[0]), "+f"(c[1]), "+f"(c[2]), "+f"(c[3])
                 : "r"(a[0]), "r"(a[1]), "r"(a[2]), "r"(a[3]),
                   "r"(b[0]), "r"(b[1]));
}

// ---------------- LayerNorm: one block per row, writes fp16 hi/lo ----------
__global__ void __launch_bounds__(256) ln_kernel(
    const float* __restrict__ x, const float* __restrict__ gamma,
    const float* __restrict__ beta)
{
    const int row = blockIdx.x, t = threadIdx.x;
    const float4* xr = (const float4*)(x + (size_t)row * Dm);
    float4 v0 = xr[t], v1 = xr[t + 256];
    float s  = v0.x + v0.y + v0.z + v0.w + v1.x + v1.y + v1.z + v1.w;
    float ss = v0.x*v0.x + v0.y*v0.y + v0.z*v0.z + v0.w*v0.w
             + v1.x*v1.x + v1.y*v1.y + v1.z*v1.z + v1.w*v1.w;
    #pragma unroll
    for (int o = 16; o; o >>= 1) {
        s  += __shfl_xor_sync(0xffffffffu, s,  o);
        ss += __shfl_xor_sync(0xffffffffu, ss, o);
    }
    __shared__ float sh[16];
    const int w = t >> 5;
    if ((t & 31) == 0) { sh[w] = s; sh[8 + w] = ss; }
    __syncthreads();
    s = 0.f; ss = 0.f;
    #pragma unroll
    for (int i = 0; i < 8; i++) { s += sh[i]; ss += sh[8 + i]; }
    const float mean = s * (1.0f / Dm);
    const float var  = ss * (1.0f / Dm) - mean * mean;
    const float rstd = rsqrtf(var + 1e-5f);

    const float4* g4 = (const float4*)gamma;
    const float4* b4 = (const float4*)beta;
    float4 G0 = g4[t], G1 = g4[t + 256], B0 = b4[t], B1 = b4[t + 256];
    float4 o0, o1;
    o0.x = (v0.x - mean) * rstd * G0.x + B0.x;
    o0.y = (v0.y - mean) * rstd * G0.y + B0.y;
    o0.z = (v0.z - mean) * rstd * G0.z + B0.z;
    o0.w = (v0.w - mean) * rstd * G0.w + B0.w;
    o1.x = (v1.x - mean) * rstd * G1.x + B1.x;
    o1.y = (v1.y - mean) * rstd * G1.y + B1.y;
    o1.z = (v1.z - mean) * rstd * G1.z + B1.z;
    o1.w = (v1.w - mean) * rstd * G1.w + B1.w;

    auto store4 = [&](float4 v, int c0) {
        __half h0,l0,h1,l1,h2,l2,h3,l3;
        hsplit(v.x,h0,l0); hsplit(v.y,h1,l1); hsplit(v.z,h2,l2); hsplit(v.w,h3,l3);
        size_t base = (size_t)row * Dm + c0;
        *(__half2*)&g_xh[base]     = __halves2half2(h0, h1);
        *(__half2*)&g_xh[base + 2] = __halves2half2(h2, h3);
        *(__half2*)&g_xl[base]     = __halves2half2(l0, l1);
        *(__half2*)&g_xl[base + 2] = __halves2half2(l2, l3);
    };
    store4(o0, t * 4);
    store4(o1, 1024 + t * 4);
}

// ---------------- W transpose + fp16 split ---------------------------------
// W: [K x N] f32 row-major -> Th/Tl: [N x K] fp16 row-major
__global__ void wconv_kernel(const float* __restrict__ W,
                             __half* __restrict__ Th,
                             __half* __restrict__ Tl, int K, int N)
{
    __shared__ float tile[32][33];
    const int tx = threadIdx.x, ty = threadIdx.y;
    const int n0 = blockIdx.x * 32, k0 = blockIdx.y * 32;
    #pragma unroll
    for (int r = 0; r < 32; r += 8)
        tile[ty + r][tx] = W[(size_t)(k0 + ty + r) * N + n0 + tx];
    __syncthreads();
    #pragma unroll
    for (int r = 0; r < 32; r += 8) {
        float v = tile[tx][ty + r];
        __half h, l; hsplit(v, h, l);
        size_t idx = (size_t)(n0 + ty + r) * K + k0 + tx;
        Th[idx] = h; Tl[idx] = l;
    }
}

// ---------------- HMMA GEMM: C = (Ah+Al)[MxK] * (Bh+Bl)^T[KxN] + bias ------
// fp16 split, 3-term (Ah*Bh + Ah*Bl + Al*Bh), fp32 accum.
// CTA 128x128, BK=64, 8 warps (2x4), warp tile 64x32, cp.async double buffer.
#define BK 64
#define LDH 72                        /* smem row stride in halves (144 B) */
#define MATB (128 * LDH * 2)          /* 18,432 B per matrix */
#define STAGEB (4 * MATB)             /* Ah, Al, Bh, Bl = 73,728 B */
#define GEMM_SMEM (2 * STAGEB)        /* 147,456 B */

__global__ void __launch_bounds__(256, 1) hgemm_kernel(
    const __half* __restrict__ Ahg, const __half* __restrict__ Alg,
    const __half* __restrict__ Bhg, const __half* __restrict__ Blg,
    const float* __restrict__ bias, float* __restrict__ C,
    int M, int N, int K)
{
    extern __shared__ char smc[];
    const uint32_t sb = cvta_smem(smc);
    const int tid = threadIdx.x, wid = tid >> 5, lid = tid & 31;
    const int m0 = blockIdx.y * 128, n0 = blockIdx.x * 128;
    const int wm = wid >> 2, wn = wid & 3;          // 2 x 4 warp grid

    const __half* gp[4] = { Ahg + (size_t)m0 * K, Alg + (size_t)m0 * K,
                            Bhg + (size_t)n0 * K, Blg + (size_t)n0 * K };

    auto load_stage = [&](int st, int kc) {
        const uint32_t base = sb + st * STAGEB;
        #pragma unroll
        for (int tI = 0; tI < 4; tI++) {
            const __half* g = gp[tI] + kc * BK;
            const uint32_t tb = base + tI * MATB;
            #pragma unroll
            for (int i = 0; i < 4; i++) {
                const int c = i * 256 + tid;           // 1024 16B chunks
                const int row = c >> 3, seg = c & 7;
                cp16(tb + (uint32_t)(row * 144 + seg * 16),
                     g + (size_t)row * K + seg * 8);
            }
        }
    };

    const int NC = K / BK;
    load_stage(0, 0); cp_commit();
    load_stage(1, 1); cp_commit();

    float acc[4][4][4];
    #pragma unroll
    for (int i = 0; i < 4; i++)
        #pragma unroll
        for (int j = 0; j < 4; j++)
            #pragma unroll
            for (int q = 0; q < 4; q++) acc[i][j][q] = 0.f;

    // ldmatrix per-lane offsets
    const int aRow = lid & 15,                 aColX = (lid & 16) ? 8 : 0;
    const int bRow = (lid & 7) + ((lid & 16) ? 8 : 0), bColX = (lid & 8) ? 8 : 0;

    for (int c = 0; c < NC; c++) {
        const int s = c & 1;
        cp_wait<1>();
        __syncthreads();
        const uint32_t stA = sb + s * STAGEB;
        const uint32_t stB = stA + 2 * MATB;

        #pragma unroll
        for (int ks = 0; ks < 4; ks++) {
            uint32_t ah[4][4], al[4][4], bh[4][2], bl[4][2];
            #pragma unroll
            for (int mi = 0; mi < 4; mi++) {
                const uint32_t ra = stA +
                    (uint32_t)(((wm * 64 + mi * 16 + aRow) * LDH + ks * 16 + aColX) * 2);
                ldsm4(ah[mi], ra);
                ldsm4(al[mi], ra + MATB);
            }
            #pragma unroll
            for (int p = 0; p < 2; p++) {
                const uint32_t rb = stB +
                    (uint32_t)(((wn * 32 + p * 16 + bRow) * LDH + ks * 16 + bColX) * 2);
                uint32_t t0[4], t1[4];
                ldsm4(t0, rb);
                ldsm4(t1, rb + MATB);
                bh[2*p][0]=t0[0]; bh[2*p][1]=t0[1]; bh[2*p+1][0]=t0[2]; bh[2*p+1][1]=t0[3];
                bl[2*p][0]=t1[0]; bl[2*p][1]=t1[1]; bl[2*p+1][0]=t1[2]; bl[2*p+1][1]=t1[3];
            }
            #pragma unroll
            for (int mi = 0; mi < 4; mi++)
                #pragma unroll
                for (int nj = 0; nj < 4; nj++) {
                    mma16816(acc[mi][nj], ah[mi], bh[nj]);
                    mma16816(acc[mi][nj], ah[mi], bl[nj]);
                    mma16816(acc[mi][nj], al[mi], bh[nj]);
                }
        }
        __syncthreads();
        if (c + 2 < NC) load_stage(s, c + 2);
        cp_commit();
    }

    // epilogue: bias add, fp32 store
    #pragma unroll
    for (int mi = 0; mi < 4; mi++) {
        const int r0 = m0 + wm * 64 + mi * 16 + (lid >> 2);
        #pragma unroll
        for (int nj = 0; nj < 4; nj++) {
            const int col = n0 + wn * 32 + nj * 8 + (lid & 3) * 2;
            const float b0 = bias[col], b1 = bias[col + 1];
            *(float2*)(C + (size_t)r0 * N + col) =
                make_float2(acc[mi][nj][0] + b0, acc[mi][nj][1] + b1);
            *(float2*)(C + (size_t)(r0 + 8) * N + col) =
                make_float2(acc[mi][nj][2] + b0, acc[mi][nj][3] + b1);
        }
    }
}

// ---------------- Flash attention (causal, fp32, f32x2 inner loops) --------
#define LDT 130

__global__ void __launch_bounds__(256, 1) flash_kernel(const float* __restrict__ qkv)
{
    extern __shared__ float sm[];
    float* Qs = sm;
    float* Ks = Qs + 64 * LDT;
    float* Vs = Ks + 64 * LDT;
    float* Ps = Vs + 64 * LDT;

    const int b = blockIdx.z, h = blockIdx.y, qt = blockIdx.x;
    const int tid = threadIdx.x, tx = tid & 15, ty = tid >> 4;
    const float scale = 0.08838834764831845f;

    const float* qbase = qkv + ((size_t)(b * Sq + qt * 64)) * QKVN + h * HDim;
    for (int i = tid; i < 64 * 64; i += 256) {
        int r = i >> 6, c = (i & 63) * 2;
        *(float2*)&Qs[r * LDT + c] = *(const float2*)(qbase + (size_t)r * QKVN + c);
    }

    float m_i[4], l_i[4];
    unsigned long long o[4][4];
    #pragma unroll
    for (int i = 0; i < 4; i++) {
        m_i[i] = -1e30f; l_i[i] = 0.f;
        #pragma unroll
        for (int j = 0; j < 4; j++) o[i][j] = 0ULL;
    }

    for (int kt = 0; kt <= qt; ++kt) {
        __syncthreads();
        const float* kbase = qkv + ((size_t)(b * Sq + kt * 64)) * QKVN + Dm + h * HDim;
        const float* vbase = kbase + Dm;
        for (int i = tid; i < 64 * 64; i += 256) {
            int r = i >> 6, c = (i & 63) * 2;
            *(float2*)&Ks[r * LDT + c] = *(const float2*)(kbase + (size_t)r * QKVN + c);
            *(float2*)&Vs[r * LDT + c] = *(const float2*)(vbase + (size_t)r * QKVN + c);
        }
        __syncthreads();

        unsigned long long sacc[4][4];
        #pragma unroll
        for (int i = 0; i < 4; i++)
            #pragma unroll
            for (int j = 0; j < 4; j++) sacc[i][j] = 0ULL;
        #pragma unroll 2
        for (int d2 = 0; d2 < 64; ++d2) {
            unsigned long long qa[4], kb[4];
            #pragma unroll
            for (int i = 0; i < 4; i++)
                qa[i] = *(const unsigned long long*)&Qs[(ty * 4 + i) * LDT + 2 * d2];
            #pragma unroll
            for (int j = 0; j < 4; j++)
                kb[j] = *(const unsigned long long*)&Ks[(j * 16 + tx) * LDT + 2 * d2];
            #pragma unroll
            for (int i = 0; i < 4; i++)
                #pragma unroll
                for (int j = 0; j < 4; j++) fma2(sacc[i][j], qa[i], kb[j]);
        }

        float s[4][4];
        #pragma unroll
        for (int i = 0; i < 4; i++)
            #pragma unroll
            for (int j = 0; j < 4; j++) {
                float2 f = up2(sacc[i][j]);
                s[i][j] = (f.x + f.y) * scale;
            }
        if (kt == qt) {
            #pragma unroll
            for (int i = 0; i < 4; i++)
                #pragma unroll
                for (int j = 0; j < 4; j++)
                    if (j * 16 + tx > ty * 4 + i) s[i][j] = -1e30f;
        }

        #pragma unroll
        for (int i = 0; i < 4; i++) {
            float rm = fmaxf(fmaxf(s[i][0], s[i][1]), fmaxf(s[i][2], s[i][3]));
            #pragma unroll
            for (int off = 8; off; off >>= 1)
                rm = fmaxf(rm, __shfl_xor_sync(0xffffffffu, rm, off));
            const float nm = fmaxf(m_i[i], rm);
            const float corr = __expf(m_i[i] - nm);
            m_i[i] = nm;
            float rs = 0.f;
            #pragma unroll
            for (int j = 0; j < 4; j++) {
                float p = __expf(s[i][j] - nm);
                Ps[(ty * 4 + i) * 64 + j * 16 + tx] = p;
                rs += p;
            }
            #pragma unroll
            for (int off = 8; off; off >>= 1)
                rs += __shfl_xor_sync(0xffffffffu, rs, off);
            l_i[i] = l_i[i] * corr + rs;
            unsigned long long c2 = pk2(corr, corr);
            #pragma unroll
            for (int j = 0; j < 4; j++) mul2(o[i][j], c2);
        }
        __syncthreads();

        #pragma unroll 2
        for (int k = 0; k < 64; ++k) {
            unsigned long long pp[4], vv[4];
            #pragma unroll
            for (int i = 0; i < 4; i++) {
                float pf = Ps[(ty * 4 + i) * 64 + k];
                pp[i] = pk2(pf, pf);
            }
            #pragma unroll
            for (int j = 0; j < 4; j++)
                vv[j] = *(const unsigned long long*)&Vs[k * LDT + j * 32 + tx * 2];
            #pragma unroll
            for (int i = 0; i < 4; i++)
                #pragma unroll
                for (int j = 0; j < 4; j++) fma2(o[i][j], pp[i], vv[j]);
        }
    }

    // epilogue: normalize, split to fp16 hi/lo for the proj GEMM
    #pragma unroll
    for (int i = 0; i < 4; i++) {
        const float inv = 1.0f / l_i[i];
        const int srow = b * Sq + qt * 64 + ty * 4 + i;
        const size_t base = (size_t)srow * Dm + h * HDim;
        #pragma unroll
        for (int j = 0; j < 4; j++) {
            float2 f = up2(o[i][j]);
            const float ox = f.x * inv, oy = f.y * inv;
            __half hx, lx, hy, ly;
            hsplit(ox, hx, lx); hsplit(oy, hy, ly);
            const size_t idx = base + j * 32 + tx * 2;
            *(__half2*)&g_ah[idx] = __halves2half2(hx, hy);
            *(__half2*)&g_al[idx] = __halves2half2(lx, ly);
        }
    }
}

// ---------------- launch ----------------------------------------------------
extern "C" void kernel_launch(void* const* d_in, const int* in_sizes, int n_in,
                              void* d_out, int out_size)
{
    const float* hs    = (const float*)d_in[0];
    const float* gamma = (const float*)d_in[1];
    const float* beta  = (const float*)d_in[2];
    const float* Wqkv  = (const float*)d_in[3];
    const float* bqkv  = (const float*)d_in[4];
    const float* Wproj = (const float*)d_in[5];
    const float* bproj = (const float*)d_in[6];
    float* out = (float*)d_out;

    void *pq, *pxh, *pxl, *pah, *pal, *pwqh, *pwql, *pwph, *pwpl;
    cudaGetSymbolAddress(&pq,  g_qkv);
    cudaGetSymbolAddress(&pxh, g_xh);  cudaGetSymbolAddress(&pxl, g_xl);
    cudaGetSymbolAddress(&pah, g_ah);  cudaGetSymbolAddress(&pal, g_al);
    cudaGetSymbolAddress(&pwqh, g_wqh); cudaGetSymbolAddress(&pwql, g_wql);
    cudaGetSymbolAddress(&pwph, g_wph); cudaGetSymbolAddress(&pwpl, g_wpl);

    // LN -> fp16 hi/lo
    ln_kernel<<<Mrows, 256>>>(hs, gamma, beta);

    // weight transpose + split
    wconv_kernel<<<dim3(QKVN / 32, Dm / 32), dim3(32, 8)>>>(
        Wqkv, (__half*)pwqh, (__half*)pwql, Dm, QKVN);
    wconv_kernel<<<dim3(Dm / 32, Dm / 32), dim3(32, 8)>>>(
        Wproj, (__half*)pwph, (__half*)pwpl, Dm, Dm);

    cudaFuncSetAttribute(hgemm_kernel,
                         cudaFuncAttributeMaxDynamicSharedMemorySize, GEMM_SMEM);

    // QKV = x @ W_qkv + b
    hgemm_kernel<<<dim3(QKVN / 128, Mrows / 128), 256, GEMM_SMEM>>>(
        (const __half*)pxh, (const __half*)pxl,
        (const __half*)pwqh, (const __half*)pwql,
        bqkv, (float*)pq, Mrows, QKVN, Dm);

    // attention
    const int FLASH_SMEM = (3 * 64 * LDT + 64 * 64) * 4;
    cudaFuncSetAttribute(flash_kernel,
                         cudaFuncAttributeMaxDynamicSharedMemorySize, FLASH_SMEM);
    flash_kernel<<<dim3(Sq / 64, Hh, Bsz), 256, FLASH_SMEM>>>((const float*)pq);

    // out = attn @ W_proj + b
    hgemm_kernel<<<dim3(Dm / 128, Mrows / 128), 256, GEMM_SMEM>>>(
        (const __half*)pah, (const __half*)pal,
        (const __half*)pwph, (const __half*)pwpl,
        bproj, out, Mrows, Dm, Dm);
}

// round 8
// speedup vs baseline: 2.8849x; 1.5811x over previous
#include <cuda_runtime.h>
#include <cuda_fp16.h>
#include <math.h>
#include <stdint.h>

#define Bsz   4
#define Sq    2048
#define Dm    2048
#define Hh    16
#define HDim  128
#define Mrows (Bsz*Sq)      /* 8192 */
#define QKVN  (3*Dm)        /* 6144 */

// ---------------- scratch (device globals; no allocation allowed) ----------
__device__ __half g_xh[(size_t)Mrows * Dm];     // LN out hi/lo (fp16 split)
__device__ __half g_xl[(size_t)Mrows * Dm];
__device__ __half g_qh[(size_t)Mrows * QKVN];   // qkv projection hi/lo
__device__ __half g_ql[(size_t)Mrows * QKVN];
__device__ __half g_ah[(size_t)Mrows * Dm];     // attn out hi/lo
__device__ __half g_al[(size_t)Mrows * Dm];
__device__ __half g_wqh[(size_t)QKVN * Dm];     // W_qkv^T hi/lo
__device__ __half g_wql[(size_t)QKVN * Dm];
__device__ __half g_wph[(size_t)Dm * Dm];       // W_proj^T hi/lo
__device__ __half g_wpl[(size_t)Dm * Dm];

// ---------------- small helpers --------------------------------------------
__device__ __forceinline__ void hsplit(float x, __half& h, __half& l) {
    h = __float2half_rn(x);
    l = __float2half_rn(x - __half2float(h));
}
__device__ __forceinline__ uint32_t packh2(__half a, __half b) {
    __half2 h = __halves2half2(a, b);
    return *(uint32_t*)&h;
}

// ---------------- Ampere-era primitives (valid on plain sm_103 target) -----
__device__ __forceinline__ uint32_t cvta_smem(const void* p) {
    return (uint32_t)__cvta_generic_to_shared(p);
}
__device__ __forceinline__ void cp16(uint32_t s, const void* g) {
    asm volatile("cp.async.cg.shared.global [%0], [%1], 16;" :: "r"(s), "l"(g));
}
__device__ __forceinline__ void cp_commit() {
    asm volatile("cp.async.commit_group;" ::: "memory");
}
template<int W> __device__ __forceinline__ void cp_wait() {
    asm volatile("cp.async.wait_group %0;" :: "n"(W) : "memory");
}
__device__ __forceinline__ void ldsm4(uint32_t* r, uint32_t addr) {
    asm volatile("ldmatrix.sync.aligned.m8n8.x4.shared.b16 {%0,%1,%2,%3}, [%4];"
                 : "=r"(r[0]), "=r"(r[1]), "=r"(r[2]), "=r"(r[3]) : "r"(addr));
}
__device__ __forceinline__ void ldsm4t(uint32_t* r, uint32_t addr) {
    asm volatile("ldmatrix.sync.aligned.m8n8.x4.trans.shared.b16 {%0,%1,%2,%3}, [%4];"
                 : "=r"(r[0]), "=r"(r[1]), "=r"(r[2]), "=r"(r[3]) : "r"(addr));
}
__device__ __forceinline__ void mma16816(float* c, const uint32_t* a, const uint32_t* b) {
    asm volatile("mma.sync.aligned.m16n8k16.row.col.f32.f16.f16.f32 "
                 "{%0,%1,%2,%3}, {%4,%5,%6,%7}, {%8,%9}, {%0,%1,%2,%3};"
                 : "+f"(c[0]), "+f"(c[1]), "+f"(c[2]), "+f"(c[3])
                 : "r"(a[0]), "r"(a[1]), "r"(a[2]), "r"(a[3]),
                   "r"(b[0]), "r"(b[1]));
}

// ---------------- LayerNorm: one block per row, writes fp16 hi/lo ----------
__global__ void __launch_bounds__(256) ln_kernel(
    const float* __restrict__ x, const float* __restrict__ gamma,
    const float* __restrict__ beta)
{
    const int row = blockIdx.x, t = threadIdx.x;
    const float4* xr = (const float4*)(x + (size_t)row * Dm);
    float4 v0 = xr[t], v1 = xr[t + 256];
    float s  = v0.x + v0.y + v0.z + v0.w + v1.x + v1.y + v1.z + v1.w;
    float ss = v0.x*v0.x + v0.y*v0.y + v0.z*v0.z + v0.w*v0.w
             + v1.x*v1.x + v1.y*v1.y + v1.z*v1.z + v1.w*v1.w;
    #pragma unroll
    for (int o = 16; o; o >>= 1) {
        s  += __shfl_xor_sync(0xffffffffu, s,  o);
        ss += __shfl_xor_sync(0xffffffffu, ss, o);
    }
    __shared__ float sh[16];
    const int w = t >> 5;
    if ((t & 31) == 0) { sh[w] = s; sh[8 + w] = ss; }
    __syncthreads();
    s = 0.f; ss = 0.f;
    #pragma unroll
    for (int i = 0; i < 8; i++) { s += sh[i]; ss += sh[8 + i]; }
    const float mean = s * (1.0f / Dm);
    const float var  = ss * (1.0f / Dm) - mean * mean;
    const float rstd = rsqrtf(var + 1e-5f);

    const float4* g4 = (const float4*)gamma;
    const float4* b4 = (const float4*)beta;
    float4 G0 = g4[t], G1 = g4[t + 256], B0 = b4[t], B1 = b4[t + 256];
    float4 o0, o1;
    o0.x = (v0.x - mean) * rstd * G0.x + B0.x;
    o0.y = (v0.y - mean) * rstd * G0.y + B0.y;
    o0.z = (v0.z - mean) * rstd * G0.z + B0.z;
    o0.w = (v0.w - mean) * rstd * G0.w + B0.w;
    o1.x = (v1.x - mean) * rstd * G1.x + B1.x;
    o1.y = (v1.y - mean) * rstd * G1.y + B1.y;
    o1.z = (v1.z - mean) * rstd * G1.z + B1.z;
    o1.w = (v1.w - mean) * rstd * G1.w + B1.w;

    auto store4 = [&](float4 v, int c0) {
        __half h0,l0,h1,l1,h2,l2,h3,l3;
        hsplit(v.x,h0,l0); hsplit(v.y,h1,l1); hsplit(v.z,h2,l2); hsplit(v.w,h3,l3);
        size_t base = (size_t)row * Dm + c0;
        *(__half2*)&g_xh[base]     = __halves2half2(h0, h1);
        *(__half2*)&g_xh[base + 2] = __halves2half2(h2, h3);
        *(__half2*)&g_xl[base]     = __halves2half2(l0, l1);
        *(__half2*)&g_xl[base + 2] = __halves2half2(l2, l3);
    };
    store4(o0, t * 4);
    store4(o1, 1024 + t * 4);
}

// ---------------- W transpose + fp16 split ---------------------------------
__global__ void wconv_kernel(const float* __restrict__ W,
                             __half* __restrict__ Th,
                             __half* __restrict__ Tl, int K, int N)
{
    __shared__ float tile[32][33];
    const int tx = threadIdx.x, ty = threadIdx.y;
    const int n0 = blockIdx.x * 32, k0 = blockIdx.y * 32;
    #pragma unroll
    for (int r = 0; r < 32; r += 8)
        tile[ty + r][tx] = W[(size_t)(k0 + ty + r) * N + n0 + tx];
    __syncthreads();
    #pragma unroll
    for (int r = 0; r < 32; r += 8) {
        float v = tile[tx][ty + r];
        __half h, l; hsplit(v, h, l);
        size_t idx = (size_t)(n0 + ty + r) * K + k0 + tx;
        Th[idx] = h; Tl[idx] = l;
    }
}

// ---------------- HMMA GEMM (3-term fp16 split), templated epilogue --------
#define BK 64
#define LDH 72
#define MATB (128 * LDH * 2)          /* 18,432 B per matrix */
#define STAGEB (4 * MATB)             /* 73,728 B */
#define GEMM_SMEM (2 * STAGEB)        /* 147,456 B */

template<bool SPLIT>
__global__ void __launch_bounds__(256, 1) hgemm_kernel(
    const __half* __restrict__ Ahg, const __half* __restrict__ Alg,
    const __half* __restrict__ Bhg, const __half* __restrict__ Blg,
    const float* __restrict__ bias, float* __restrict__ C,
    __half* __restrict__ Oh, __half* __restrict__ Ol,
    int M, int N, int K)
{
    extern __shared__ char smc[];
    const uint32_t sb = cvta_smem(smc);
    const int tid = threadIdx.x, wid = tid >> 5, lid = tid & 31;
    const int m0 = blockIdx.y * 128, n0 = blockIdx.x * 128;
    const int wm = wid >> 2, wn = wid & 3;

    const __half* gp[4] = { Ahg + (size_t)m0 * K, Alg + (size_t)m0 * K,
                            Bhg + (size_t)n0 * K, Blg + (size_t)n0 * K };

    auto load_stage = [&](int st, int kc) {
        const uint32_t base = sb + st * STAGEB;
        #pragma unroll
        for (int tI = 0; tI < 4; tI++) {
            const __half* g = gp[tI] + kc * BK;
            const uint32_t tb = base + tI * MATB;
            #pragma unroll
            for (int i = 0; i < 4; i++) {
                const int c = i * 256 + tid;
                const int row = c >> 3, seg = c & 7;
                cp16(tb + (uint32_t)(row * 144 + seg * 16),
                     g + (size_t)row * K + seg * 8);
            }
        }
    };

    const int NC = K / BK;
    load_stage(0, 0); cp_commit();
    load_stage(1, 1); cp_commit();

    float acc[4][4][4];
    #pragma unroll
    for (int i = 0; i < 4; i++)
        #pragma unroll
        for (int j = 0; j < 4; j++)
            #pragma unroll
            for (int q = 0; q < 4; q++) acc[i][j][q] = 0.f;

    const int aRow = lid & 15, aColX = (lid & 16) ? 8 : 0;
    const int bRow = (lid & 7) + ((lid & 16) ? 8 : 0), bColX = (lid & 8) ? 8 : 0;

    for (int c = 0; c < NC; c++) {
        const int s = c & 1;
        cp_wait<1>();
        __syncthreads();
        const uint32_t stA = sb + s * STAGEB;
        const uint32_t stB = stA + 2 * MATB;

        #pragma unroll
        for (int ks = 0; ks < 4; ks++) {
            uint32_t ah[4][4], al[4][4], bh[4][2], bl[4][2];
            #pragma unroll
            for (int mi = 0; mi < 4; mi++) {
                const uint32_t ra = stA +
                    (uint32_t)(((wm * 64 + mi * 16 + aRow) * LDH + ks * 16 + aColX) * 2);
                ldsm4(ah[mi], ra);
                ldsm4(al[mi], ra + MATB);
            }
            #pragma unroll
            for (int p = 0; p < 2; p++) {
                const uint32_t rb = stB +
                    (uint32_t)(((wn * 32 + p * 16 + bRow) * LDH + ks * 16 + bColX) * 2);
                uint32_t t0[4], t1[4];
                ldsm4(t0, rb);
                ldsm4(t1, rb + MATB);
                bh[2*p][0]=t0[0]; bh[2*p][1]=t0[1]; bh[2*p+1][0]=t0[2]; bh[2*p+1][1]=t0[3];
                bl[2*p][0]=t1[0]; bl[2*p][1]=t1[1]; bl[2*p+1][0]=t1[2]; bl[2*p+1][1]=t1[3];
            }
            #pragma unroll
            for (int mi = 0; mi < 4; mi++)
                #pragma unroll
                for (int nj = 0; nj < 4; nj++) {
                    mma16816(acc[mi][nj], ah[mi], bh[nj]);
                    mma16816(acc[mi][nj], ah[mi], bl[nj]);
                    mma16816(acc[mi][nj], al[mi], bh[nj]);
                }
        }
        __syncthreads();
        if (c + 2 < NC) load_stage(s, c + 2);
        cp_commit();
    }

    #pragma unroll
    for (int mi = 0; mi < 4; mi++) {
        const int r0 = m0 + wm * 64 + mi * 16 + (lid >> 2);
        #pragma unroll
        for (int nj = 0; nj < 4; nj++) {
            const int col = n0 + wn * 32 + nj * 8 + (lid & 3) * 2;
            const float b0 = bias[col], b1 = bias[col + 1];
            const float v00 = acc[mi][nj][0] + b0, v01 = acc[mi][nj][1] + b1;
            const float v10 = acc[mi][nj][2] + b0, v11 = acc[mi][nj][3] + b1;
            if (SPLIT) {
                __half h0,l0,h1,l1;
                hsplit(v00,h0,l0); hsplit(v01,h1,l1);
                *(__half2*)&Oh[(size_t)r0 * N + col] = __halves2half2(h0, h1);
                *(__half2*)&Ol[(size_t)r0 * N + col] = __halves2half2(l0, l1);
                hsplit(v10,h0,l0); hsplit(v11,h1,l1);
                *(__half2*)&Oh[(size_t)(r0+8) * N + col] = __halves2half2(h0, h1);
                *(__half2*)&Ol[(size_t)(r0+8) * N + col] = __halves2half2(l0, l1);
            } else {
                *(float2*)(C + (size_t)r0 * N + col) = make_float2(v00, v01);
                *(float2*)(C + (size_t)(r0 + 8) * N + col) = make_float2(v10, v11);
            }
        }
    }
}

// ---------------- Flash attention on HMMA (causal, fp16-split 3-term) ------
// CTA: 128 q rows x one (b,h); 8 warps x m16. K-tile 64, double-buffered.
#define FLD 136                       /* smem row stride in halves (272 B) */
#define FQL (128*FLD)                 /* Ql offset (halves) */
#define FST0 (2*128*FLD)              /* stage 0 offset */
#define FKL (64*FLD)
#define FVH (2*64*FLD)
#define FVL (3*64*FLD)
#define FSTAGE (4*64*FLD)
#define FLASH_SMEM ((FST0 + 2*FSTAGE)*2)   /* 208,896 B */

__global__ void __launch_bounds__(256, 1) flash_kernel(
    const __half* __restrict__ qh, const __half* __restrict__ ql)
{
    extern __shared__ char fsmc[];
    const uint32_t sb = cvta_smem(fsmc);
    const int tid = threadIdx.x, wid = tid >> 5, lid = tid & 31;
    const int b = blockIdx.z, h = blockIdx.y, qt = blockIdx.x;
    const int m0w = wid * 16;
    const size_t rowQ0 = (size_t)b * Sq + qt * 128;
    const int cQ = h * HDim, cK = Dm + h * HDim, cV = 2 * Dm + h * HDim;

    // Q tiles (hi+lo): 8 chunks per thread per array
    #pragma unroll
    for (int i = 0; i < 8; i++) {
        const int c = i * 256 + tid;
        const int r = c >> 4, seg = c & 15;
        const uint32_t so = (uint32_t)(r * FLD + seg * 8) * 2;
        const size_t g = (rowQ0 + r) * QKVN + cQ + seg * 8;
        cp16(sb + so, qh + g);
        cp16(sb + FQL*2 + so, ql + g);
    }

    auto load_kv = [&](int st, int kt) {
        const size_t rowK0 = (size_t)b * Sq + kt * 64;
        const uint32_t base = sb + (uint32_t)(FST0 + st * FSTAGE) * 2;
        #pragma unroll
        for (int i = 0; i < 4; i++) {
            const int c = i * 256 + tid;
            const int r = c >> 4, seg = c & 15;
            const uint32_t so = (uint32_t)(r * FLD + seg * 8) * 2;
            const size_t gk = (rowK0 + r) * QKVN + cK + seg * 8;
            const size_t gv = (rowK0 + r) * QKVN + cV + seg * 8;
            cp16(base + so,          qh + gk);
            cp16(base + FKL*2 + so,  ql + gk);
            cp16(base + FVH*2 + so,  qh + gv);
            cp16(base + FVL*2 + so,  ql + gv);
        }
    };

    const int NT = 2 * qt + 2;
    load_kv(0, 0); cp_commit();
    load_kv(1, 1); cp_commit();

    float o[16][4];
    #pragma unroll
    for (int i = 0; i < 16; i++)
        #pragma unroll
        for (int j = 0; j < 4; j++) o[i][j] = 0.f;
    float mA = -1e30f, mB = -1e30f, lA = 0.f, lB = 0.f;

    const int aRow = lid & 15, aColX = (lid & 16) ? 8 : 0;
    const int bRow = (lid & 7) + ((lid & 16) ? 8 : 0), bColX = (lid & 8) ? 8 : 0;
    const int rA = lid >> 2;
    const int qgA = qt * 128 + m0w + rA, qgB = qgA + 8;
    const float scale = 0.08838834764831845f;   // 1/sqrt(128)

    for (int kt = 0; kt < NT; ++kt) {
        cp_wait<1>();
        __syncthreads();
        const bool active = (kt * 64) < (qt * 128 + m0w + 16);
        if (active) {
            const uint32_t stb = sb + (uint32_t)(FST0 + (kt & 1) * FSTAGE) * 2;
            // ---- scores = Q K^T (3-term) ----
            float sc[8][4];
            #pragma unroll
            for (int i = 0; i < 8; i++)
                #pragma unroll
                for (int j = 0; j < 4; j++) sc[i][j] = 0.f;
            #pragma unroll
            for (int ks = 0; ks < 8; ks++) {
                uint32_t ah[4], al[4];
                const uint32_t qa = sb +
                    (uint32_t)(((m0w + aRow) * FLD + ks * 16 + aColX) * 2);
                ldsm4(ah, qa);
                ldsm4(al, qa + FQL*2);
                #pragma unroll
                for (int np = 0; np < 4; np++) {
                    uint32_t kh4[4], kl4[4];
                    const uint32_t ka = stb +
                        (uint32_t)(((np * 16 + bRow) * FLD + ks * 16 + bColX) * 2);
                    ldsm4(kh4, ka);
                    ldsm4(kl4, ka + FKL*2);
                    uint32_t bh0[2] = {kh4[0], kh4[1]}, bh1[2] = {kh4[2], kh4[3]};
                    uint32_t bl0[2] = {kl4[0], kl4[1]}, bl1[2] = {kl4[2], kl4[3]};
                    mma16816(sc[2*np],   ah, bh0); mma16816(sc[2*np],   ah, bl0);
                    mma16816(sc[2*np],   al, bh0);
                    mma16816(sc[2*np+1], ah, bh1); mma16816(sc[2*np+1], ah, bl1);
                    mma16816(sc[2*np+1], al, bh1);
                }
            }
            // ---- scale + causal mask (only on diagonal tiles) ----
            #pragma unroll
            for (int nt = 0; nt < 8; nt++)
                #pragma unroll
                for (int j = 0; j < 4; j++) sc[nt][j] *= scale;
            if (kt >= 2 * qt) {
                #pragma unroll
                for (int nt = 0; nt < 8; nt++) {
                    const int kg = kt * 64 + nt * 8 + 2 * (lid & 3);
                    if (kg     > qgA) sc[nt][0] = -1e30f;
                    if (kg + 1 > qgA) sc[nt][1] = -1e30f;
                    if (kg     > qgB) sc[nt][2] = -1e30f;
                    if (kg + 1 > qgB) sc[nt][3] = -1e30f;
                }
            }
            // ---- online softmax (rows rA, rB per thread quad) ----
            float rmA = -1e30f, rmB = -1e30f;
            #pragma unroll
            for (int nt = 0; nt < 8; nt++) {
                rmA = fmaxf(rmA, fmaxf(sc[nt][0], sc[nt][1]));
                rmB = fmaxf(rmB, fmaxf(sc[nt][2], sc[nt][3]));
            }
            rmA = fmaxf(rmA, __shfl_xor_sync(0xffffffffu, rmA, 1));
            rmA = fmaxf(rmA, __shfl_xor_sync(0xffffffffu, rmA, 2));
            rmB = fmaxf(rmB, __shfl_xor_sync(0xffffffffu, rmB, 1));
            rmB = fmaxf(rmB, __shfl_xor_sync(0xffffffffu, rmB, 2));
            const float nmA = fmaxf(mA, rmA), nmB = fmaxf(mB, rmB);
            const float corrA = __expf(mA - nmA), corrB = __expf(mB - nmB);
            mA = nmA; mB = nmB;
            float rsA = 0.f, rsB = 0.f;
            #pragma unroll
            for (int nt = 0; nt < 8; nt++) {
                sc[nt][0] = __expf(sc[nt][0] - nmA); rsA += sc[nt][0];
                sc[nt][1] = __expf(sc[nt][1] - nmA); rsA += sc[nt][1];
                sc[nt][2] = __expf(sc[nt][2] - nmB); rsB += sc[nt][2];
                sc[nt][3] = __expf(sc[nt][3] - nmB); rsB += sc[nt][3];
            }
            rsA += __shfl_xor_sync(0xffffffffu, rsA, 1);
            rsA += __shfl_xor_sync(0xffffffffu, rsA, 2);
            rsB += __shfl_xor_sync(0xffffffffu, rsB, 1);
            rsB += __shfl_xor_sync(0xffffffffu, rsB, 2);
            lA = lA * corrA + rsA;
            lB = lB * corrB + rsB;
            #pragma unroll
            for (int d = 0; d < 16; d++) {
                o[d][0] *= corrA; o[d][1] *= corrA;
                o[d][2] *= corrB; o[d][3] *= corrB;
            }
            // ---- O += P V (3-term, P split in registers) ----
            #pragma unroll
            for (int k2 = 0; k2 < 4; k2++) {
                const float* t0 = sc[2*k2];
                const float* t1 = sc[2*k2+1];
                __half p00 = __float2half_rn(t0[0]), p01 = __float2half_rn(t0[1]);
                __half p02 = __float2half_rn(t0[2]), p03 = __float2half_rn(t0[3]);
                __half p10 = __float2half_rn(t1[0]), p11 = __float2half_rn(t1[1]);
                __half p12 = __float2half_rn(t1[2]), p13 = __float2half_rn(t1[3]);
                uint32_t aPh[4], aPl[4];
                aPh[0] = packh2(p00, p01); aPh[1] = packh2(p02, p03);
                aPh[2] = packh2(p10, p11); aPh[3] = packh2(p12, p13);
                aPl[0] = packh2(__float2half_rn(t0[0]-__half2float(p00)),
                                __float2half_rn(t0[1]-__half2float(p01)));
                aPl[1] = packh2(__float2half_rn(t0[2]-__half2float(p02)),
                                __float2half_rn(t0[3]-__half2float(p03)));
                aPl[2] = packh2(__float2half_rn(t1[0]-__half2float(p10)),
                                __float2half_rn(t1[1]-__half2float(p11)));
                aPl[3] = packh2(__float2half_rn(t1[2]-__half2float(p12)),
                                __float2half_rn(t1[3]-__half2float(p13)));
                #pragma unroll
                for (int dp = 0; dp < 8; dp++) {
                    uint32_t vh4[4], vl4[4];
                    const uint32_t va = stb + FVH*2 +
                        (uint32_t)(((k2 * 16 + aRow) * FLD + dp * 16 + aColX) * 2);
                    ldsm4t(vh4, va);
                    ldsm4t(vl4, va + (FVL - FVH) * 2);
                    uint32_t b0[2] = {vh4[0], vh4[1]}, b1[2] = {vh4[2], vh4[3]};
                    uint32_t c0[2] = {vl4[0], vl4[1]}, c1[2] = {vl4[2], vl4[3]};
                    mma16816(o[2*dp],   aPh, b0); mma16816(o[2*dp],   aPh, c0);
                    mma16816(o[2*dp],   aPl, b0);
                    mma16816(o[2*dp+1], aPh, b1); mma16816(o[2*dp+1], aPh, c1);
                    mma16816(o[2*dp+1], aPl, b1);
                }
            }
        }
        __syncthreads();
        if (kt + 2 < NT) load_kv(kt & 1, kt + 2);
        cp_commit();
    }

    // ---- epilogue: normalize, split to fp16 hi/lo for proj GEMM ----
    const float invA = 1.f / lA, invB = 1.f / lB;
    const size_t gA = (rowQ0 + m0w + rA) * Dm + h * HDim;
    const size_t gB = gA + (size_t)8 * Dm;
    #pragma unroll
    for (int nt = 0; nt < 16; nt++) {
        const int col = nt * 8 + 2 * (lid & 3);
        float x0 = o[nt][0] * invA, x1 = o[nt][1] * invA;
        __half h0,l0,h1,l1;
        hsplit(x0,h0,l0); hsplit(x1,h1,l1);
        *(__half2*)&g_ah[gA + col] = __halves2half2(h0, h1);
        *(__half2*)&g_al[gA + col] = __halves2half2(l0, l1);
        float x2 = o[nt][2] * invB, x3 = o[nt][3] * invB;
        hsplit(x2,h0,l0); hsplit(x3,h1,l1);
        *(__half2*)&g_ah[gB + col] = __halves2half2(h0, h1);
        *(__half2*)&g_al[gB + col] = __halves2half2(l0, l1);
    }
}

// ---------------- launch ----------------------------------------------------
extern "C" void kernel_launch(void* const* d_in, const int* in_sizes, int n_in,
                              void* d_out, int out_size)
{
    const float* hs    = (const float*)d_in[0];
    const float* gamma = (const float*)d_in[1];
    const float* beta  = (const float*)d_in[2];
    const float* Wqkv  = (const float*)d_in[3];
    const float* bqkv  = (const float*)d_in[4];
    const float* Wproj = (const float*)d_in[5];
    const float* bproj = (const float*)d_in[6];
    float* out = (float*)d_out;

    void *pxh,*pxl,*pqh,*pql,*pah,*pal,*pwqh,*pwql,*pwph,*pwpl;
    cudaGetSymbolAddress(&pxh, g_xh);  cudaGetSymbolAddress(&pxl, g_xl);
    cudaGetSymbolAddress(&pqh, g_qh);  cudaGetSymbolAddress(&pql, g_ql);
    cudaGetSymbolAddress(&pah, g_ah);  cudaGetSymbolAddress(&pal, g_al);
    cudaGetSymbolAddress(&pwqh, g_wqh); cudaGetSymbolAddress(&pwql, g_wql);
    cudaGetSymbolAddress(&pwph, g_wph); cudaGetSymbolAddress(&pwpl, g_wpl);

    // LN -> fp16 hi/lo
    ln_kernel<<<Mrows, 256>>>(hs, gamma, beta);

    // weight transpose + split
    wconv_kernel<<<dim3(QKVN / 32, Dm / 32), dim3(32, 8)>>>(
        Wqkv, (__half*)pwqh, (__half*)pwql, Dm, QKVN);
    wconv_kernel<<<dim3(Dm / 32, Dm / 32), dim3(32, 8)>>>(
        Wproj, (__half*)pwph, (__half*)pwpl, Dm, Dm);

    cudaFuncSetAttribute(hgemm_kernel<true>,
                         cudaFuncAttributeMaxDynamicSharedMemorySize, GEMM_SMEM);
    cudaFuncSetAttribute(hgemm_kernel<false>,
                         cudaFuncAttributeMaxDynamicSharedMemorySize, GEMM_SMEM);

    // QKV = x @ W_qkv + b  -> fp16 hi/lo
    hgemm_kernel<true><<<dim3(QKVN / 128, Mrows / 128), 256, GEMM_SMEM>>>(
        (const __half*)pxh, (const __half*)pxl,
        (const __half*)pwqh, (const __half*)pwql,
        bqkv, nullptr, (__half*)pqh, (__half*)pql, Mrows, QKVN, Dm);

    // attention (HMMA flash)
    cudaFuncSetAttribute(flash_kernel,
                         cudaFuncAttributeMaxDynamicSharedMemorySize, FLASH_SMEM);
    flash_kernel<<<dim3(Sq / 128, Hh, Bsz), 256, FLASH_SMEM>>>(
        (const __half*)pqh, (const __half*)pql);

    // out = attn @ W_proj + b  -> f32
    hgemm_kernel<false><<<dim3(Dm / 128, Mrows / 128), 256, GEMM_SMEM>>>(
        (const __half*)pah, (const __half*)pal,
        (const __half*)pwph, (const __half*)pwpl,
        bproj, out, nullptr, nullptr, Mrows, Dm, Dm);
}

// round 10
// speedup vs baseline: 4.0527x; 1.4048x over previous
#include <cuda_runtime.h>
#include <cuda_fp16.h>
#include <math.h>
#include <stdint.h>

#define Bsz   4
#define Sq    2048
#define Dm    2048
#define Hh    16
#define HDim  128
#define Mrows (Bsz*Sq)      /* 8192 */
#define QKVN  (3*Dm)        /* 6144 */

// ---------------- scratch (device globals; no allocation allowed) ----------
__device__ __half g_xh[(size_t)Mrows * Dm];     // LN out hi/lo (fp16 split)
__device__ __half g_xl[(size_t)Mrows * Dm];
__device__ __half g_qh[(size_t)Mrows * QKVN];   // qkv projection hi/lo
__device__ __half g_ql[(size_t)Mrows * QKVN];   // (lo only consumed for Q cols)
__device__ __half g_ah[(size_t)Mrows * Dm];     // attn out hi/lo
__device__ __half g_al[(size_t)Mrows * Dm];
__device__ __half g_wqh[(size_t)QKVN * Dm];     // W_qkv^T hi
__device__ __half g_wph[(size_t)Dm * Dm];       // W_proj^T hi

// ---------------- small helpers --------------------------------------------
__device__ __forceinline__ void hsplit(float x, __half& h, __half& l) {
    h = __float2half_rn(x);
    l = __float2half_rn(x - __half2float(h));
}
__device__ __forceinline__ uint32_t packh2(__half a, __half b) {
    __half2 h = __halves2half2(a, b);
    return *(uint32_t*)&h;
}

// ---------------- Ampere-era primitives (valid on plain sm_103 target) -----
__device__ __forceinline__ uint32_t cvta_smem(const void* p) {
    return (uint32_t)__cvta_generic_to_shared(p);
}
__device__ __forceinline__ void cp16(uint32_t s, const void* g) {
    asm volatile("cp.async.cg.shared.global [%0], [%1], 16;" :: "r"(s), "l"(g));
}
__device__ __forceinline__ void cp_commit() {
    asm volatile("cp.async.commit_group;" ::: "memory");
}
template<int W> __device__ __forceinline__ void cp_wait() {
    asm volatile("cp.async.wait_group %0;" :: "n"(W) : "memory");
}
__device__ __forceinline__ void ldsm4(uint32_t* r, uint32_t addr) {
    asm volatile("ldmatrix.sync.aligned.m8n8.x4.shared.b16 {%0,%1,%2,%3}, [%4];"
                 : "=r"(r[0]), "=r"(r[1]), "=r"(r[2]), "=r"(r[3]) : "r"(addr));
}
__device__ __forceinline__ void ldsm4t(uint32_t* r, uint32_t addr) {
    asm volatile("ldmatrix.sync.aligned.m8n8.x4.trans.shared.b16 {%0,%1,%2,%3}, [%4];"
                 : "=r"(r[0]), "=r"(r[1]), "=r"(r[2]), "=r"(r[3]) : "r"(addr));
}
__device__ __forceinline__ void mma16816(float* c, const uint32_t* a, const uint32_t* b) {
    asm volatile("mma.sync.aligned.m16n8k16.row.col.f32.f16.f16.f32 "
                 "{%0,%1,%2,%3}, {%4,%5,%6,%7}, {%8,%9}, {%0,%1,%2,%3};"
                 : "+f"(c[0]), "+f"(c[1]), "+f"(c[2]), "+f"(c[3])
                 : "r"(a[0]), "r"(a[1]), "r"(a[2]), "r"(a[3]),
                   "r"(b[0]), "r"(b[1]));
}

// ---------------- LayerNorm: one block per row, writes fp16 hi/lo ----------
__global__ void __launch_bounds__(256) ln_kernel(
    const float* __restrict__ x, const float* __restrict__ gamma,
    const float* __restrict__ beta)
{
    const int row = blockIdx.x, t = threadIdx.x;
    const float4* xr = (const float4*)(x + (size_t)row * Dm);
    float4 v0 = xr[t], v1 = xr[t + 256];
    float s  = v0.x + v0.y + v0.z + v0.w + v1.x + v1.y + v1.z + v1.w;
    float ss = v0.x*v0.x + v0.y*v0.y + v0.z*v0.z + v0.w*v0.w
             + v1.x*v1.x + v1.y*v1.y + v1.z*v1.z + v1.w*v1.w;
    #pragma unroll
    for (int o = 16; o; o >>= 1) {
        s  += __shfl_xor_sync(0xffffffffu, s,  o);
        ss += __shfl_xor_sync(0xffffffffu, ss, o);
    }
    __shared__ float sh[16];
    const int w = t >> 5;
    if ((t & 31) == 0) { sh[w] = s; sh[8 + w] = ss; }
    __syncthreads();
    s = 0.f; ss = 0.f;
    #pragma unroll
    for (int i = 0; i < 8; i++) { s += sh[i]; ss += sh[8 + i]; }
    const float mean = s * (1.0f / Dm);
    const float var  = ss * (1.0f / Dm) - mean * mean;
    const float rstd = rsqrtf(var + 1e-5f);

    const float4* g4 = (const float4*)gamma;
    const float4* b4 = (const float4*)beta;
    float4 G0 = g4[t], G1 = g4[t + 256], B0 = b4[t], B1 = b4[t + 256];
    float4 o0, o1;
    o0.x = (v0.x - mean) * rstd * G0.x + B0.x;
    o0.y = (v0.y - mean) * rstd * G0.y + B0.y;
    o0.z = (v0.z - mean) * rstd * G0.z + B0.z;
    o0.w = (v0.w - mean) * rstd * G0.w + B0.w;
    o1.x = (v1.x - mean) * rstd * G1.x + B1.x;
    o1.y = (v1.y - mean) * rstd * G1.y + B1.y;
    o1.z = (v1.z - mean) * rstd * G1.z + B1.z;
    o1.w = (v1.w - mean) * rstd * G1.w + B1.w;

    auto store4 = [&](float4 v, int c0) {
        __half h0,l0,h1,l1,h2,l2,h3,l3;
        hsplit(v.x,h0,l0); hsplit(v.y,h1,l1); hsplit(v.z,h2,l2); hsplit(v.w,h3,l3);
        size_t base = (size_t)row * Dm + c0;
        *(__half2*)&g_xh[base]     = __halves2half2(h0, h1);
        *(__half2*)&g_xh[base + 2] = __halves2half2(h2, h3);
        *(__half2*)&g_xl[base]     = __halves2half2(l0, l1);
        *(__half2*)&g_xl[base + 2] = __halves2half2(l2, l3);
    };
    store4(o0, t * 4);
    store4(o1, 1024 + t * 4);
}

// ---------------- W transpose + fp16 convert (hi only) ---------------------
__global__ void wconv_kernel(const float* __restrict__ W,
                             __half* __restrict__ Th, int K, int N)
{
    __shared__ float tile[32][33];
    const int tx = threadIdx.x, ty = threadIdx.y;
    const int n0 = blockIdx.x * 32, k0 = blockIdx.y * 32;
    #pragma unroll
    for (int r = 0; r < 32; r += 8)
        tile[ty + r][tx] = W[(size_t)(k0 + ty + r) * N + n0 + tx];
    __syncthreads();
    #pragma unroll
    for (int r = 0; r < 32; r += 8) {
        Th[(size_t)(n0 + ty + r) * K + k0 + tx] = __float2half_rn(tile[tx][ty + r]);
    }
}

// ---------------- HMMA GEMM: C = (Ah+Al)[MxK] * Bh^T[KxN] + bias -----------
// 2-term fp16 split (== exact A times fp16 B), fp32 accum.
// CTA 128x128, BK=64, 8 warps (2x4), warp tile 64x32, 3-stage cp.async.
#define BK 64
#define LDH 72
#define MATB (128 * LDH * 2)          /* 18,432 B per matrix */
#define STAGEB (3 * MATB)             /* Ah, Al, Bh = 55,296 B */
#define GEMM_SMEM (3 * STAGEB)        /* 165,888 B */

template<bool SPLIT>
__global__ void __launch_bounds__(256, 1) hgemm_kernel(
    const __half* __restrict__ Ahg, const __half* __restrict__ Alg,
    const __half* __restrict__ Bhg,
    const float* __restrict__ bias, float* __restrict__ C,
    __half* __restrict__ Oh, __half* __restrict__ Ol,
    int M, int N, int K, int loN)
{
    extern __shared__ char smc[];
    const uint32_t sb = cvta_smem(smc);
    const int tid = threadIdx.x, wid = tid >> 5, lid = tid & 31;
    const int m0 = blockIdx.y * 128, n0 = blockIdx.x * 128;
    const int wm = wid >> 2, wn = wid & 3;

    const __half* gp[3] = { Ahg + (size_t)m0 * K, Alg + (size_t)m0 * K,
                            Bhg + (size_t)n0 * K };

    auto load_stage = [&](int st, int kc) {
        const uint32_t base = sb + st * STAGEB;
        #pragma unroll
        for (int tI = 0; tI < 3; tI++) {
            const __half* g = gp[tI] + kc * BK;
            const uint32_t tb = base + tI * MATB;
            #pragma unroll
            for (int i = 0; i < 4; i++) {
                const int c = i * 256 + tid;
                const int row = c >> 3, seg = c & 7;
                cp16(tb + (uint32_t)(row * 144 + seg * 16),
                     g + (size_t)row * K + seg * 8);
            }
        }
    };

    const int NC = K / BK;                  /* 32 */
    load_stage(0, 0); cp_commit();
    load_stage(1, 1); cp_commit();
    load_stage(2, 2); cp_commit();

    float acc[4][4][4];
    #pragma unroll
    for (int i = 0; i < 4; i++)
        #pragma unroll
        for (int j = 0; j < 4; j++)
            #pragma unroll
            for (int q = 0; q < 4; q++) acc[i][j][q] = 0.f;

    const int aRow = lid & 15, aColX = (lid & 16) ? 8 : 0;
    const int bRow = (lid & 7) + ((lid & 16) ? 8 : 0), bColX = (lid & 8) ? 8 : 0;

    for (int c = 0; c < NC; c++) {
        const int s = c % 3;
        cp_wait<2>();
        __syncthreads();
        const uint32_t stA = sb + s * STAGEB;
        const uint32_t stB = stA + 2 * MATB;

        #pragma unroll
        for (int ks = 0; ks < 4; ks++) {
            uint32_t ah[4][4], al[4][4], bh[4][2];
            #pragma unroll
            for (int mi = 0; mi < 4; mi++) {
                const uint32_t ra = stA +
                    (uint32_t)(((wm * 64 + mi * 16 + aRow) * LDH + ks * 16 + aColX) * 2);
                ldsm4(ah[mi], ra);
                ldsm4(al[mi], ra + MATB);
            }
            #pragma unroll
            for (int p = 0; p < 2; p++) {
                const uint32_t rb = stB +
                    (uint32_t)(((wn * 32 + p * 16 + bRow) * LDH + ks * 16 + bColX) * 2);
                uint32_t t0[4];
                ldsm4(t0, rb);
                bh[2*p][0]=t0[0]; bh[2*p][1]=t0[1]; bh[2*p+1][0]=t0[2]; bh[2*p+1][1]=t0[3];
            }
            #pragma unroll
            for (int mi = 0; mi < 4; mi++)
                #pragma unroll
                for (int nj = 0; nj < 4; nj++) {
                    mma16816(acc[mi][nj], ah[mi], bh[nj]);
                    mma16816(acc[mi][nj], al[mi], bh[nj]);
                }
        }
        __syncthreads();
        if (c + 3 < NC) load_stage(s, c + 3);
        cp_commit();
    }

    const bool wantLo = SPLIT && (n0 < loN);
    #pragma unroll
    for (int mi = 0; mi < 4; mi++) {
        const int r0 = m0 + wm * 64 + mi * 16 + (lid >> 2);
        #pragma unroll
        for (int nj = 0; nj < 4; nj++) {
            const int col = n0 + wn * 32 + nj * 8 + (lid & 3) * 2;
            const float b0 = bias[col], b1 = bias[col + 1];
            const float v00 = acc[mi][nj][0] + b0, v01 = acc[mi][nj][1] + b1;
            const float v10 = acc[mi][nj][2] + b0, v11 = acc[mi][nj][3] + b1;
            if (SPLIT) {
                __half h0,l0,h1,l1;
                hsplit(v00,h0,l0); hsplit(v01,h1,l1);
                *(__half2*)&Oh[(size_t)r0 * N + col] = __halves2half2(h0, h1);
                if (wantLo) *(__half2*)&Ol[(size_t)r0 * N + col] = __halves2half2(l0, l1);
                hsplit(v10,h0,l0); hsplit(v11,h1,l1);
                *(__half2*)&Oh[(size_t)(r0+8) * N + col] = __halves2half2(h0, h1);
                if (wantLo) *(__half2*)&Ol[(size_t)(r0+8) * N + col] = __halves2half2(l0, l1);
            } else {
                *(float2*)(C + (size_t)r0 * N + col) = make_float2(v00, v01);
                *(float2*)(C + (size_t)(r0 + 8) * N + col) = make_float2(v10, v11);
            }
        }
    }
}

// ---------------- Flash attention on HMMA (causal, 2-term split) -----------
// CTA: 128 q rows x one (b,h); 8 warps x m16. K-tile 64, 3-stage KV (hi only).
#define FLD 136                       /* smem row stride in halves (272 B) */
#define FQL (128*FLD)                 /* Ql offset (halves) */
#define FST0 (2*128*FLD)              /* KV stage 0 offset (halves) */
#define FVH (64*FLD)                  /* V offset within stage */
#define FSTAGE (2*64*FLD)             /* Kh + Vh */
#define FLASH_SMEM ((FST0 + 3*FSTAGE)*2)   /* 174,080 B */

__global__ void __launch_bounds__(256, 1) flash_kernel(
    const __half* __restrict__ qh, const __half* __restrict__ ql)
{
    extern __shared__ char fsmc[];
    const uint32_t sb = cvta_smem(fsmc);
    const int tid = threadIdx.x, wid = tid >> 5, lid = tid & 31;
    const int b = blockIdx.z, h = blockIdx.y, qt = blockIdx.x;
    const int m0w = wid * 16;
    const size_t rowQ0 = (size_t)b * Sq + qt * 128;
    const int cQ = h * HDim, cK = Dm + h * HDim, cV = 2 * Dm + h * HDim;

    // Q tiles (hi+lo)
    #pragma unroll
    for (int i = 0; i < 8; i++) {
        const int c = i * 256 + tid;
        const int r = c >> 4, seg = c & 15;
        const uint32_t so = (uint32_t)(r * FLD + seg * 8) * 2;
        const size_t g = (rowQ0 + r) * QKVN + cQ + seg * 8;
        cp16(sb + so, qh + g);
        cp16(sb + FQL*2 + so, ql + g);
    }

    auto load_kv = [&](int st, int kt) {
        const size_t rowK0 = (size_t)b * Sq + kt * 64;
        const uint32_t base = sb + (uint32_t)(FST0 + st * FSTAGE) * 2;
        #pragma unroll
        for (int i = 0; i < 4; i++) {
            const int c = i * 256 + tid;
            const int r = c >> 4, seg = c & 15;
            const uint32_t so = (uint32_t)(r * FLD + seg * 8) * 2;
            cp16(base + so,         qh + (rowK0 + r) * QKVN + cK + seg * 8);
            cp16(base + FVH*2 + so, qh + (rowK0 + r) * QKVN + cV + seg * 8);
        }
    };

    const int NT = 2 * qt + 2;
    load_kv(0, 0); cp_commit();
    if (1 < NT) load_kv(1, 1); cp_commit();
    if (2 < NT) load_kv(2, 2); cp_commit();

    float o[16][4];
    #pragma unroll
    for (int i = 0; i < 16; i++)
        #pragma unroll
        for (int j = 0; j < 4; j++) o[i][j] = 0.f;
    float mA = -1e30f, mB = -1e30f, lA = 0.f, lB = 0.f;

    const int aRow = lid & 15, aColX = (lid & 16) ? 8 : 0;
    const int bRow = (lid & 7) + ((lid & 16) ? 8 : 0), bColX = (lid & 8) ? 8 : 0;
    const int rA = lid >> 2;
    const int qgA = qt * 128 + m0w + rA, qgB = qgA + 8;
    const float scale = 0.08838834764831845f;   // 1/sqrt(128)

    for (int kt = 0; kt < NT; ++kt) {
        cp_wait<2>();
        __syncthreads();
        const bool active = (kt * 64) < (qt * 128 + m0w + 16);
        if (active) {
            const uint32_t stb = sb + (uint32_t)(FST0 + (kt % 3) * FSTAGE) * 2;
            // ---- scores = Q K^T (2-term: (Qh+Ql)·Kh) ----
            float sc[8][4];
            #pragma unroll
            for (int i = 0; i < 8; i++)
                #pragma unroll
                for (int j = 0; j < 4; j++) sc[i][j] = 0.f;
            #pragma unroll
            for (int ks = 0; ks < 8; ks++) {
                uint32_t ah[4], al[4];
                const uint32_t qa = sb +
                    (uint32_t)(((m0w + aRow) * FLD + ks * 16 + aColX) * 2);
                ldsm4(ah, qa);
                ldsm4(al, qa + FQL*2);
                #pragma unroll
                for (int np = 0; np < 4; np++) {
                    uint32_t kh4[4];
                    const uint32_t ka = stb +
                        (uint32_t)(((np * 16 + bRow) * FLD + ks * 16 + bColX) * 2);
                    ldsm4(kh4, ka);
                    uint32_t bh0[2] = {kh4[0], kh4[1]}, bh1[2] = {kh4[2], kh4[3]};
                    mma16816(sc[2*np],   ah, bh0); mma16816(sc[2*np],   al, bh0);
                    mma16816(sc[2*np+1], ah, bh1); mma16816(sc[2*np+1], al, bh1);
                }
            }
            // ---- scale + causal mask (diagonal tiles only) ----
            #pragma unroll
            for (int nt = 0; nt < 8; nt++)
                #pragma unroll
                for (int j = 0; j < 4; j++) sc[nt][j] *= scale;
            if (kt >= 2 * qt) {
                #pragma unroll
                for (int nt = 0; nt < 8; nt++) {
                    const int kg = kt * 64 + nt * 8 + 2 * (lid & 3);
                    if (kg     > qgA) sc[nt][0] = -1e30f;
                    if (kg + 1 > qgA) sc[nt][1] = -1e30f;
                    if (kg     > qgB) sc[nt][2] = -1e30f;
                    if (kg + 1 > qgB) sc[nt][3] = -1e30f;
                }
            }
            // ---- online softmax ----
            float rmA = -1e30f, rmB = -1e30f;
            #pragma unroll
            for (int nt = 0; nt < 8; nt++) {
                rmA = fmaxf(rmA, fmaxf(sc[nt][0], sc[nt][1]));
                rmB = fmaxf(rmB, fmaxf(sc[nt][2], sc[nt][3]));
            }
            rmA = fmaxf(rmA, __shfl_xor_sync(0xffffffffu, rmA, 1));
            rmA = fmaxf(rmA, __shfl_xor_sync(0xffffffffu, rmA, 2));
            rmB = fmaxf(rmB, __shfl_xor_sync(0xffffffffu, rmB, 1));
            rmB = fmaxf(rmB, __shfl_xor_sync(0xffffffffu, rmB, 2));
            const float nmA = fmaxf(mA, rmA), nmB = fmaxf(mB, rmB);
            const float corrA = __expf(mA - nmA), corrB = __expf(mB - nmB);
            mA = nmA; mB = nmB;
            float rsA = 0.f, rsB = 0.f;
            #pragma unroll
            for (int nt = 0; nt < 8; nt++) {
                sc[nt][0] = __expf(sc[nt][0] - nmA); rsA += sc[nt][0];
                sc[nt][1] = __expf(sc[nt][1] - nmA); rsA += sc[nt][1];
                sc[nt][2] = __expf(sc[nt][2] - nmB); rsB += sc[nt][2];
                sc[nt][3] = __expf(sc[nt][3] - nmB); rsB += sc[nt][3];
            }
            rsA += __shfl_xor_sync(0xffffffffu, rsA, 1);
            rsA += __shfl_xor_sync(0xffffffffu, rsA, 2);
            rsB += __shfl_xor_sync(0xffffffffu, rsB, 1);
            rsB += __shfl_xor_sync(0xffffffffu, rsB, 2);
            lA = lA * corrA + rsA;
            lB = lB * corrB + rsB;
            #pragma unroll
            for (int d = 0; d < 16; d++) {
                o[d][0] *= corrA; o[d][1] *= corrA;
                o[d][2] *= corrB; o[d][3] *= corrB;
            }
            // ---- O += P V (2-term: (Ph+Pl)·Vh) ----
            #pragma unroll
            for (int k2 = 0; k2 < 4; k2++) {
                const float* t0 = sc[2*k2];
                const float* t1 = sc[2*k2+1];
                __half p00 = __float2half_rn(t0[0]), p01 = __float2half_rn(t0[1]);
                __half p02 = __float2half_rn(t0[2]), p03 = __float2half_rn(t0[3]);
                __half p10 = __float2half_rn(t1[0]), p11 = __float2half_rn(t1[1]);
                __half p12 = __float2half_rn(t1[2]), p13 = __float2half_rn(t1[3]);
                uint32_t aPh[4], aPl[4];
                aPh[0] = packh2(p00, p01); aPh[1] = packh2(p02, p03);
                aPh[2] = packh2(p10, p11); aPh[3] = packh2(p12, p13);
                aPl[0] = packh2(__float2half_rn(t0[0]-__half2float(p00)),
                                __float2half_rn(t0[1]-__half2float(p01)));
                aPl[1] = packh2(__float2half_rn(t0[2]-__half2float(p02)),
                                __float2half_rn(t0[3]-__half2float(p03)));
                aPl[2] = packh2(__float2half_rn(t1[0]-__half2float(p10)),
                                __float2half_rn(t1[1]-__half2float(p11)));
                aPl[3] = packh2(__float2half_rn(t1[2]-__half2float(p12)),
                                __float2half_rn(t1[3]-__half2float(p13)));
                #pragma unroll
                for (int dp = 0; dp < 8; dp++) {
                    uint32_t vh4[4];
                    const uint32_t va = stb + FVH*2 +
                        (uint32_t)(((k2 * 16 + aRow) * FLD + dp * 16 + aColX) * 2);
                    ldsm4t(vh4, va);
                    uint32_t b0[2] = {vh4[0], vh4[1]}, b1[2] = {vh4[2], vh4[3]};
                    mma16816(o[2*dp],   aPh, b0); mma16816(o[2*dp],   aPl, b0);
                    mma16816(o[2*dp+1], aPh, b1); mma16816(o[2*dp+1], aPl, b1);
                }
            }
        }
        __syncthreads();
        if (kt + 3 < NT) load_kv(kt % 3, kt + 3);
        cp_commit();
    }

    // ---- epilogue: normalize, split to fp16 hi/lo for proj GEMM ----
    const float invA = 1.f / lA, invB = 1.f / lB;
    const size_t gA = (rowQ0 + m0w + rA) * Dm + h * HDim;
    const size_t gB = gA + (size_t)8 * Dm;
    #pragma unroll
    for (int nt = 0; nt < 16; nt++) {
        const int col = nt * 8 + 2 * (lid & 3);
        float x0 = o[nt][0] * invA, x1 = o[nt][1] * invA;
        __half h0,l0,h1,l1;
        hsplit(x0,h0,l0); hsplit(x1,h1,l1);
        *(__half2*)&g_ah[gA + col] = __halves2half2(h0, h1);
        *(__half2*)&g_al[gA + col] = __halves2half2(l0, l1);
        float x2 = o[nt][2] * invB, x3 = o[nt][3] * invB;
        hsplit(x2,h0,l0); hsplit(x3,h1,l1);
        *(__half2*)&g_ah[gB + col] = __halves2half2(h0, h1);
        *(__half2*)&g_al[gB + col] = __halves2half2(l0, l1);
    }
}

// ---------------- launch ----------------------------------------------------
extern "C" void kernel_launch(void* const* d_in, const int* in_sizes, int n_in,
                              void* d_out, int out_size)
{
    const float* hs    = (const float*)d_in[0];
    const float* gamma = (const float*)d_in[1];
    const float* beta  = (const float*)d_in[2];
    const float* Wqkv  = (const float*)d_in[3];
    const float* bqkv  = (const float*)d_in[4];
    const float* Wproj = (const float*)d_in[5];
    const float* bproj = (const float*)d_in[6];
    float* out = (float*)d_out;

    void *pxh,*pxl,*pqh,*pql,*pah,*pal,*pwqh,*pwph;
    cudaGetSymbolAddress(&pxh, g_xh);  cudaGetSymbolAddress(&pxl, g_xl);
    cudaGetSymbolAddress(&pqh, g_qh);  cudaGetSymbolAddress(&pql, g_ql);
    cudaGetSymbolAddress(&pah, g_ah);  cudaGetSymbolAddress(&pal, g_al);
    cudaGetSymbolAddress(&pwqh, g_wqh);
    cudaGetSymbolAddress(&pwph, g_wph);

    // LN -> fp16 hi/lo
    ln_kernel<<<Mrows, 256>>>(hs, gamma, beta);

    // weight transpose + fp16 (hi only)
    wconv_kernel<<<dim3(QKVN / 32, Dm / 32), dim3(32, 8)>>>(
        Wqkv, (__half*)pwqh, Dm, QKVN);
    wconv_kernel<<<dim3(Dm / 32, Dm / 32), dim3(32, 8)>>>(
        Wproj, (__half*)pwph, Dm, Dm);

    cudaFuncSetAttribute(hgemm_kernel<true>,
                         cudaFuncAttributeMaxDynamicSharedMemorySize, GEMM_SMEM);
    cudaFuncSetAttribute(hgemm_kernel<false>,
                         cudaFuncAttributeMaxDynamicSharedMemorySize, GEMM_SMEM);

    // QKV = x @ W_qkv + b  -> fp16 hi (+ lo for Q columns only)
    hgemm_kernel<true><<<dim3(QKVN / 128, Mrows / 128), 256, GEMM_SMEM>>>(
        (const __half*)pxh, (const __half*)pxl, (const __half*)pwqh,
        bqkv, nullptr, (__half*)pqh, (__half*)pql, Mrows, QKVN, Dm, Dm);

    // attention (HMMA flash, 2-term)
    cudaFuncSetAttribute(flash_kernel,
                         cudaFuncAttributeMaxDynamicSharedMemorySize, FLASH_SMEM);
    flash_kernel<<<dim3(Sq / 128, Hh, Bsz), 256, FLASH_SMEM>>>(
        (const __half*)pqh, (const __half*)pql);

    // out = attn @ W_proj + b  -> f32
    hgemm_kernel<false><<<dim3(Dm / 128, Mrows / 128), 256, GEMM_SMEM>>>(
        (const __half*)pah, (const __half*)pal, (const __half*)pwph,
        bproj, out, nullptr, nullptr, Mrows, Dm, Dm, 0);
}

// round 12
// speedup vs baseline: 4.6042x; 1.1361x over previous
#include <cuda_runtime.h>
#include <cuda_fp16.h>
#include <math.h>
#include <stdint.h>

#define Bsz   4
#define Sq    2048
#define Dm    2048
#define Hh    16
#define HDim  128
#define Mrows (Bsz*Sq)      /* 8192 */
#define QKVN  (3*Dm)        /* 6144 */

// ---------------- scratch (device globals; no allocation allowed) ----------
__device__ __half g_xh[(size_t)Mrows * Dm];     // LN out hi/lo (fp16 split)
__device__ __half g_xl[(size_t)Mrows * Dm];
__device__ __half g_qh[(size_t)Mrows * QKVN];   // qkv projection hi/lo
__device__ __half g_ql[(size_t)Mrows * QKVN];   // (lo only consumed for Q cols)
__device__ __half g_ah[(size_t)Mrows * Dm];     // attn out hi/lo
__device__ __half g_al[(size_t)Mrows * Dm];
__device__ __half g_wqh[(size_t)QKVN * Dm];     // W_qkv^T hi
__device__ __half g_wph[(size_t)Dm * Dm];       // W_proj^T hi

// ---------------- small helpers --------------------------------------------
__device__ __forceinline__ void hsplit(float x, __half& h, __half& l) {
    h = __float2half_rn(x);
    l = __float2half_rn(x - __half2float(h));
}
__device__ __forceinline__ uint32_t packh2(__half a, __half b) {
    __half2 h = __halves2half2(a, b);
    return *(uint32_t*)&h;
}

// ---------------- Ampere-era primitives (valid on plain sm_103 target) -----
__device__ __forceinline__ uint32_t cvta_smem(const void* p) {
    return (uint32_t)__cvta_generic_to_shared(p);
}
__device__ __forceinline__ void cp16(uint32_t s, const void* g) {
    asm volatile("cp.async.cg.shared.global [%0], [%1], 16;" :: "r"(s), "l"(g));
}
__device__ __forceinline__ void cp_commit() {
    asm volatile("cp.async.commit_group;" ::: "memory");
}
template<int W> __device__ __forceinline__ void cp_wait() {
    asm volatile("cp.async.wait_group %0;" :: "n"(W) : "memory");
}
__device__ __forceinline__ void ldsm4(uint32_t* r, uint32_t addr) {
    asm volatile("ldmatrix.sync.aligned.m8n8.x4.shared.b16 {%0,%1,%2,%3}, [%4];"
                 : "=r"(r[0]), "=r"(r[1]), "=r"(r[2]), "=r"(r[3]) : "r"(addr));
}
__device__ __forceinline__ void ldsm4t(uint32_t* r, uint32_t addr) {
    asm volatile("ldmatrix.sync.aligned.m8n8.x4.trans.shared.b16 {%0,%1,%2,%3}, [%4];"
                 : "=r"(r[0]), "=r"(r[1]), "=r"(r[2]), "=r"(r[3]) : "r"(addr));
}
__device__ __forceinline__ void mma16816(float* c, const uint32_t* a, const uint32_t* b) {
    asm volatile("mma.sync.aligned.m16n8k16.row.col.f32.f16.f16.f32 "
                 "{%0,%1,%2,%3}, {%4,%5,%6,%7}, {%8,%9}, {%0,%1,%2,%3};"
                 : "+f"(c[0]), "+f"(c[1]), "+f"(c[2]), "+f"(c[3])
                 : "r"(a[0]), "r"(a[1]), "r"(a[2]), "r"(a[3]),
                   "r"(b[0]), "r"(b[1]));
}

// ---------------- LayerNorm: one block per row, writes fp16 hi/lo ----------
__global__ void __launch_bounds__(256) ln_kernel(
    const float* __restrict__ x, const float* __restrict__ gamma,
    const float* __restrict__ beta)
{
    const int row = blockIdx.x, t = threadIdx.x;
    const float4* xr = (const float4*)(x + (size_t)row * Dm);
    float4 v0 = xr[t], v1 = xr[t + 256];
    float s  = v0.x + v0.y + v0.z + v0.w + v1.x + v1.y + v1.z + v1.w;
    float ss = v0.x*v0.x + v0.y*v0.y + v0.z*v0.z + v0.w*v0.w
             + v1.x*v1.x + v1.y*v1.y + v1.z*v1.z + v1.w*v1.w;
    #pragma unroll
    for (int o = 16; o; o >>= 1) {
        s  += __shfl_xor_sync(0xffffffffu, s,  o);
        ss += __shfl_xor_sync(0xffffffffu, ss, o);
    }
    __shared__ float sh[16];
    const int w = t >> 5;
    if ((t & 31) == 0) { sh[w] = s; sh[8 + w] = ss; }
    __syncthreads();
    s = 0.f; ss = 0.f;
    #pragma unroll
    for (int i = 0; i < 8; i++) { s += sh[i]; ss += sh[8 + i]; }
    const float mean = s * (1.0f / Dm);
    const float var  = ss * (1.0f / Dm) - mean * mean;
    const float rstd = rsqrtf(var + 1e-5f);

    const float4* g4 = (const float4*)gamma;
    const float4* b4 = (const float4*)beta;
    float4 G0 = g4[t], G1 = g4[t + 256], B0 = b4[t], B1 = b4[t + 256];
    float4 o0, o1;
    o0.x = (v0.x - mean) * rstd * G0.x + B0.x;
    o0.y = (v0.y - mean) * rstd * G0.y + B0.y;
    o0.z = (v0.z - mean) * rstd * G0.z + B0.z;
    o0.w = (v0.w - mean) * rstd * G0.w + B0.w;
    o1.x = (v1.x - mean) * rstd * G1.x + B1.x;
    o1.y = (v1.y - mean) * rstd * G1.y + B1.y;
    o1.z = (v1.z - mean) * rstd * G1.z + B1.z;
    o1.w = (v1.w - mean) * rstd * G1.w + B1.w;

    auto store4 = [&](float4 v, int c0) {
        __half h0,l0,h1,l1,h2,l2,h3,l3;
        hsplit(v.x,h0,l0); hsplit(v.y,h1,l1); hsplit(v.z,h2,l2); hsplit(v.w,h3,l3);
        size_t base = (size_t)row * Dm + c0;
        *(__half2*)&g_xh[base]     = __halves2half2(h0, h1);
        *(__half2*)&g_xh[base + 2] = __halves2half2(h2, h3);
        *(__half2*)&g_xl[base]     = __halves2half2(l0, l1);
        *(__half2*)&g_xl[base + 2] = __halves2half2(l2, l3);
    };
    store4(o0, t * 4);
    store4(o1, 1024 + t * 4);
}

// ---------------- W transpose + fp16 convert (hi only) ---------------------
__global__ void wconv_kernel(const float* __restrict__ W,
                             __half* __restrict__ Th, int K, int N)
{
    __shared__ float tile[32][33];
    const int tx = threadIdx.x, ty = threadIdx.y;
    const int n0 = blockIdx.x * 32, k0 = blockIdx.y * 32;
    #pragma unroll
    for (int r = 0; r < 32; r += 8)
        tile[ty + r][tx] = W[(size_t)(k0 + ty + r) * N + n0 + tx];
    __syncthreads();
    #pragma unroll
    for (int r = 0; r < 32; r += 8) {
        Th[(size_t)(n0 + ty + r) * K + k0 + tx] = __float2half_rn(tile[tx][ty + r]);
    }
}

// ---------------- HMMA GEMM: C = (Ah+Al)[MxK] * Bh^T[KxN] + bias -----------
// 2-term fp16 split, fp32 accum. CTA 128x128, BK=64, 8 warps (2x4),
// 2-stage cp.async, 2 CTAs/SM (register-lean inner loop).
#define BK 64
#define LDH 72
#define MATB (128 * LDH * 2)          /* 18,432 B per matrix */
#define STAGEB (3 * MATB)             /* Ah, Al, Bh = 55,296 B */
#define GEMM_SMEM (2 * STAGEB)        /* 110,592 B -> 2 CTAs/SM */

template<bool SPLIT>
__global__ void __launch_bounds__(256, 2) hgemm_kernel(
    const __half* __restrict__ Ahg, const __half* __restrict__ Alg,
    const __half* __restrict__ Bhg,
    const float* __restrict__ bias, float* __restrict__ C,
    __half* __restrict__ Oh, __half* __restrict__ Ol,
    int M, int N, int K, int loN)
{
    extern __shared__ char smc[];
    const uint32_t sb = cvta_smem(smc);
    const int tid = threadIdx.x, wid = tid >> 5, lid = tid & 31;
    const int m0 = blockIdx.y * 128, n0 = blockIdx.x * 128;
    const int wm = wid >> 2, wn = wid & 3;

    const __half* gp[3] = { Ahg + (size_t)m0 * K, Alg + (size_t)m0 * K,
                            Bhg + (size_t)n0 * K };

    auto load_stage = [&](int st, int kc) {
        const uint32_t base = sb + st * STAGEB;
        #pragma unroll
        for (int tI = 0; tI < 3; tI++) {
            const __half* g = gp[tI] + kc * BK;
            const uint32_t tb = base + tI * MATB;
            #pragma unroll
            for (int i = 0; i < 4; i++) {
                const int c = i * 256 + tid;
                const int row = c >> 3, seg = c & 7;
                cp16(tb + (uint32_t)(row * 144 + seg * 16),
                     g + (size_t)row * K + seg * 8);
            }
        }
    };

    const int NC = K / BK;                  /* 32 */
    load_stage(0, 0); cp_commit();
    load_stage(1, 1); cp_commit();

    float acc[4][4][4];
    #pragma unroll
    for (int i = 0; i < 4; i++)
        #pragma unroll
        for (int j = 0; j < 4; j++)
            #pragma unroll
            for (int q = 0; q < 4; q++) acc[i][j][q] = 0.f;

    const int aRow = lid & 15, aColX = (lid & 16) ? 8 : 0;
    const int bRow = (lid & 7) + ((lid & 16) ? 8 : 0), bColX = (lid & 8) ? 8 : 0;

    for (int c = 0; c < NC; c++) {
        const int s = c & 1;
        cp_wait<1>();
        __syncthreads();
        const uint32_t stA = sb + s * STAGEB;
        const uint32_t stB = stA + 2 * MATB;

        #pragma unroll
        for (int ks = 0; ks < 4; ks++) {
            // B fragments first (8 regs live)
            uint32_t bh[4][2];
            #pragma unroll
            for (int p = 0; p < 2; p++) {
                const uint32_t rb = stB +
                    (uint32_t)(((wn * 32 + p * 16 + bRow) * LDH + ks * 16 + bColX) * 2);
                uint32_t t0[4];
                ldsm4(t0, rb);
                bh[2*p][0]=t0[0]; bh[2*p][1]=t0[1]; bh[2*p+1][0]=t0[2]; bh[2*p+1][1]=t0[3];
            }
            // per-mi A fragments (8 regs live), fire 8 MMAs immediately
            #pragma unroll
            for (int mi = 0; mi < 4; mi++) {
                uint32_t ah[4], al[4];
                const uint32_t ra = stA +
                    (uint32_t)(((wm * 64 + mi * 16 + aRow) * LDH + ks * 16 + aColX) * 2);
                ldsm4(ah, ra);
                ldsm4(al, ra + MATB);
                #pragma unroll
                for (int nj = 0; nj < 4; nj++) {
                    mma16816(acc[mi][nj], ah, bh[nj]);
                    mma16816(acc[mi][nj], al, bh[nj]);
                }
            }
        }
        __syncthreads();
        if (c + 2 < NC) load_stage(s, c + 2);
        cp_commit();
    }

    const bool wantLo = SPLIT && (n0 < loN);
    #pragma unroll
    for (int mi = 0; mi < 4; mi++) {
        const int r0 = m0 + wm * 64 + mi * 16 + (lid >> 2);
        #pragma unroll
        for (int nj = 0; nj < 4; nj++) {
            const int col = n0 + wn * 32 + nj * 8 + (lid & 3) * 2;
            const float b0 = bias[col], b1 = bias[col + 1];
            const float v00 = acc[mi][nj][0] + b0, v01 = acc[mi][nj][1] + b1;
            const float v10 = acc[mi][nj][2] + b0, v11 = acc[mi][nj][3] + b1;
            if (SPLIT) {
                __half h0,l0,h1,l1;
                hsplit(v00,h0,l0); hsplit(v01,h1,l1);
                *(__half2*)&Oh[(size_t)r0 * N + col] = __halves2half2(h0, h1);
                if (wantLo) *(__half2*)&Ol[(size_t)r0 * N + col] = __halves2half2(l0, l1);
                hsplit(v10,h0,l0); hsplit(v11,h1,l1);
                *(__half2*)&Oh[(size_t)(r0+8) * N + col] = __halves2half2(h0, h1);
                if (wantLo) *(__half2*)&Ol[(size_t)(r0+8) * N + col] = __halves2half2(l0, l1);
            } else {
                *(float2*)(C + (size_t)r0 * N + col) = make_float2(v00, v01);
                *(float2*)(C + (size_t)(r0 + 8) * N + col) = make_float2(v10, v11);
            }
        }
    }
}

// ---------------- Flash attention on HMMA (causal, 2-term split) -----------
// CTA: 128 q rows x one (b,h); 8 warps x m16. K-tile 64, 3-stage KV (hi only).
// q-tiles launched largest-first to trim the tail wave.
#define FLD 136                       /* smem row stride in halves (272 B) */
#define FQL (128*FLD)                 /* Ql offset (halves) */
#define FST0 (2*128*FLD)              /* KV stage 0 offset (halves) */
#define FVH (64*FLD)                  /* V offset within stage */
#define FSTAGE (2*64*FLD)             /* Kh + Vh */
#define FLASH_SMEM ((FST0 + 3*FSTAGE)*2)   /* 174,080 B */

__global__ void __launch_bounds__(256, 1) flash_kernel(
    const __half* __restrict__ qh, const __half* __restrict__ ql)
{
    extern __shared__ char fsmc[];
    const uint32_t sb = cvta_smem(fsmc);
    const int tid = threadIdx.x, wid = tid >> 5, lid = tid & 31;
    const int b = blockIdx.z, h = blockIdx.y;
    const int qt = gridDim.x - 1 - blockIdx.x;    /* big tiles first */
    const int m0w = wid * 16;
    const size_t rowQ0 = (size_t)b * Sq + qt * 128;
    const int cQ = h * HDim, cK = Dm + h * HDim, cV = 2 * Dm + h * HDim;

    // Q tiles (hi+lo)
    #pragma unroll
    for (int i = 0; i < 8; i++) {
        const int c = i * 256 + tid;
        const int r = c >> 4, seg = c & 15;
        const uint32_t so = (uint32_t)(r * FLD + seg * 8) * 2;
        const size_t g = (rowQ0 + r) * QKVN + cQ + seg * 8;
        cp16(sb + so, qh + g);
        cp16(sb + FQL*2 + so, ql + g);
    }

    auto load_kv = [&](int st, int kt) {
        const size_t rowK0 = (size_t)b * Sq + kt * 64;
        const uint32_t base = sb + (uint32_t)(FST0 + st * FSTAGE) * 2;
        #pragma unroll
        for (int i = 0; i < 4; i++) {
            const int c = i * 256 + tid;
            const int r = c >> 4, seg = c & 15;
            const uint32_t so = (uint32_t)(r * FLD + seg * 8) * 2;
            cp16(base + so,         qh + (rowK0 + r) * QKVN + cK + seg * 8);
            cp16(base + FVH*2 + so, qh + (rowK0 + r) * QKVN + cV + seg * 8);
        }
    };

    const int NT = 2 * qt + 2;
    load_kv(0, 0); cp_commit();
    if (1 < NT) load_kv(1, 1); cp_commit();
    if (2 < NT) load_kv(2, 2); cp_commit();

    float o[16][4];
    #pragma unroll
    for (int i = 0; i < 16; i++)
        #pragma unroll
        for (int j = 0; j < 4; j++) o[i][j] = 0.f;
    float mA = -1e30f, mB = -1e30f, lA = 0.f, lB = 0.f;

    const int aRow = lid & 15, aColX = (lid & 16) ? 8 : 0;
    const int bRow = (lid & 7) + ((lid & 16) ? 8 : 0), bColX = (lid & 8) ? 8 : 0;
    const int rA = lid >> 2;
    const int qgA = qt * 128 + m0w + rA, qgB = qgA + 8;
    const float scale = 0.08838834764831845f;   // 1/sqrt(128)

    for (int kt = 0; kt < NT; ++kt) {
        cp_wait<2>();
        __syncthreads();
        const bool active = (kt * 64) < (qt * 128 + m0w + 16);
        if (active) {
            const uint32_t stb = sb + (uint32_t)(FST0 + (kt % 3) * FSTAGE) * 2;
            // ---- scores = Q K^T (2-term: (Qh+Ql)·Kh) ----
            float sc[8][4];
            #pragma unroll
            for (int i = 0; i < 8; i++)
                #pragma unroll
                for (int j = 0; j < 4; j++) sc[i][j] = 0.f;
            #pragma unroll
            for (int ks = 0; ks < 8; ks++) {
                uint32_t ah[4], al[4];
                const uint32_t qa = sb +
                    (uint32_t)(((m0w + aRow) * FLD + ks * 16 + aColX) * 2);
                ldsm4(ah, qa);
                ldsm4(al, qa + FQL*2);
                #pragma unroll
                for (int np = 0; np < 4; np++) {
                    uint32_t kh4[4];
                    const uint32_t ka = stb +
                        (uint32_t)(((np * 16 + bRow) * FLD + ks * 16 + bColX) * 2);
                    ldsm4(kh4, ka);
                    uint32_t bh0[2] = {kh4[0], kh4[1]}, bh1[2] = {kh4[2], kh4[3]};
                    mma16816(sc[2*np],   ah, bh0); mma16816(sc[2*np],   al, bh0);
                    mma16816(sc[2*np+1], ah, bh1); mma16816(sc[2*np+1], al, bh1);
                }
            }
            // ---- scale + causal mask (diagonal tiles only) ----
            #pragma unroll
            for (int nt = 0; nt < 8; nt++)
                #pragma unroll
                for (int j = 0; j < 4; j++) sc[nt][j] *= scale;
            if (kt >= 2 * qt) {
                #pragma unroll
                for (int nt = 0; nt < 8; nt++) {
                    const int kg = kt * 64 + nt * 8 + 2 * (lid & 3);
                    if (kg     > qgA) sc[nt][0] = -1e30f;
                    if (kg + 1 > qgA) sc[nt][1] = -1e30f;
                    if (kg     > qgB) sc[nt][2] = -1e30f;
                    if (kg + 1 > qgB) sc[nt][3] = -1e30f;
                }
            }
            // ---- online softmax ----
            float rmA = -1e30f, rmB = -1e30f;
            #pragma unroll
            for (int nt = 0; nt < 8; nt++) {
                rmA = fmaxf(rmA, fmaxf(sc[nt][0], sc[nt][1]));
                rmB = fmaxf(rmB, fmaxf(sc[nt][2], sc[nt][3]));
            }
            rmA = fmaxf(rmA, __shfl_xor_sync(0xffffffffu, rmA, 1));
            rmA = fmaxf(rmA, __shfl_xor_sync(0xffffffffu, rmA, 2));
            rmB = fmaxf(rmB, __shfl_xor_sync(0xffffffffu, rmB, 1));
            rmB = fmaxf(rmB, __shfl_xor_sync(0xffffffffu, rmB, 2));
            const float nmA = fmaxf(mA, rmA), nmB = fmaxf(mB, rmB);
            const float corrA = __expf(mA - nmA), corrB = __expf(mB - nmB);
            mA = nmA; mB = nmB;
            float rsA = 0.f, rsB = 0.f;
            #pragma unroll
            for (int nt = 0; nt < 8; nt++) {
                sc[nt][0] = __expf(sc[nt][0] - nmA); rsA += sc[nt][0];
                sc[nt][1] = __expf(sc[nt][1] - nmA); rsA += sc[nt][1];
                sc[nt][2] = __expf(sc[nt][2] - nmB); rsB += sc[nt][2];
                sc[nt][3] = __expf(sc[nt][3] - nmB); rsB += sc[nt][3];
            }
            rsA += __shfl_xor_sync(0xffffffffu, rsA, 1);
            rsA += __shfl_xor_sync(0xffffffffu, rsA, 2);
            rsB += __shfl_xor_sync(0xffffffffu, rsB, 1);
            rsB += __shfl_xor_sync(0xffffffffu, rsB, 2);
            lA = lA * corrA + rsA;
            lB = lB * corrB + rsB;
            #pragma unroll
            for (int d = 0; d < 16; d++) {
                o[d][0] *= corrA; o[d][1] *= corrA;
                o[d][2] *= corrB; o[d][3] *= corrB;
            }
            // ---- O += P V (2-term: (Ph+Pl)·Vh) ----
            #pragma unroll
            for (int k2 = 0; k2 < 4; k2++) {
                const float* t0 = sc[2*k2];
                const float* t1 = sc[2*k2+1];
                __half p00 = __float2half_rn(t0[0]), p01 = __float2half_rn(t0[1]);
                __half p02 = __float2half_rn(t0[2]), p03 = __float2half_rn(t0[3]);
                __half p10 = __float2half_rn(t1[0]), p11 = __float2half_rn(t1[1]);
                __half p12 = __float2half_rn(t1[2]), p13 = __float2half_rn(t1[3]);
                uint32_t aPh[4], aPl[4];
                aPh[0] = packh2(p00, p01); aPh[1] = packh2(p02, p03);
                aPh[2] = packh2(p10, p11); aPh[3] = packh2(p12, p13);
                aPl[0] = packh2(__float2half_rn(t0[0]-__half2float(p00)),
                                __float2half_rn(t0[1]-__half2float(p01)));
                aPl[1] = packh2(__float2half_rn(t0[2]-__half2float(p02)),
                                __float2half_rn(t0[3]-__half2float(p03)));
                aPl[2] = packh2(__float2half_rn(t1[0]-__half2float(p10)),
                                __float2half_rn(t1[1]-__half2float(p11)));
                aPl[3] = packh2(__float2half_rn(t1[2]-__half2float(p12)),
                                __float2half_rn(t1[3]-__half2float(p13)));
                #pragma unroll
                for (int dp = 0; dp < 8; dp++) {
                    uint32_t vh4[4];
                    const uint32_t va = stb + FVH*2 +
                        (uint32_t)(((k2 * 16 + aRow) * FLD + dp * 16 + aColX) * 2);
                    ldsm4t(vh4, va);
                    uint32_t b0[2] = {vh4[0], vh4[1]}, b1[2] = {vh4[2], vh4[3]};
                    mma16816(o[2*dp],   aPh, b0); mma16816(o[2*dp],   aPl, b0);
                    mma16816(o[2*dp+1], aPh, b1); mma16816(o[2*dp+1], aPl, b1);
                }
            }
        }
        __syncthreads();
        if (kt + 3 < NT) load_kv(kt % 3, kt + 3);
        cp_commit();
    }

    // ---- epilogue: normalize, split to fp16 hi/lo for proj GEMM ----
    const float invA = 1.f / lA, invB = 1.f / lB;
    const size_t gA = (rowQ0 + m0w + rA) * Dm + h * HDim;
    const size_t gB = gA + (size_t)8 * Dm;
    #pragma unroll
    for (int nt = 0; nt < 16; nt++) {
        const int col = nt * 8 + 2 * (lid & 3);
        float x0 = o[nt][0] * invA, x1 = o[nt][1] * invA;
        __half h0,l0,h1,l1;
        hsplit(x0,h0,l0); hsplit(x1,h1,l1);
        *(__half2*)&g_ah[gA + col] = __halves2half2(h0, h1);
        *(__half2*)&g_al[gA + col] = __halves2half2(l0, l1);
        float x2 = o[nt][2] * invB, x3 = o[nt][3] * invB;
        hsplit(x2,h0,l0); hsplit(x3,h1,l1);
        *(__half2*)&g_ah[gB + col] = __halves2half2(h0, h1);
        *(__half2*)&g_al[gB + col] = __halves2half2(l0, l1);
    }
}

// ---------------- launch ----------------------------------------------------
extern "C" void kernel_launch(void* const* d_in, const int* in_sizes, int n_in,
                              void* d_out, int out_size)
{
    const float* hs    = (const float*)d_in[0];
    const float* gamma = (const float*)d_in[1];
    const float* beta  = (const float*)d_in[2];
    const float* Wqkv  = (const float*)d_in[3];
    const float* bqkv  = (const float*)d_in[4];
    const float* Wproj = (const float*)d_in[5];
    const float* bproj = (const float*)d_in[6];
    float* out = (float*)d_out;

    void *pxh,*pxl,*pqh,*pql,*pah,*pal,*pwqh,*pwph;
    cudaGetSymbolAddress(&pxh, g_xh);  cudaGetSymbolAddress(&pxl, g_xl);
    cudaGetSymbolAddress(&pqh, g_qh);  cudaGetSymbolAddress(&pql, g_ql);
    cudaGetSymbolAddress(&pah, g_ah);  cudaGetSymbolAddress(&pal, g_al);
    cudaGetSymbolAddress(&pwqh, g_wqh);
    cudaGetSymbolAddress(&pwph, g_wph);

    // LN -> fp16 hi/lo
    ln_kernel<<<Mrows, 256>>>(hs, gamma, beta);

    // weight transpose + fp16 (hi only)
    wconv_kernel<<<dim3(QKVN / 32, Dm / 32), dim3(32, 8)>>>(
        Wqkv, (__half*)pwqh, Dm, QKVN);
    wconv_kernel<<<dim3(Dm / 32, Dm / 32), dim3(32, 8)>>>(
        Wproj, (__half*)pwph, Dm, Dm);

    cudaFuncSetAttribute(hgemm_kernel<true>,
                         cudaFuncAttributeMaxDynamicSharedMemorySize, GEMM_SMEM);
    cudaFuncSetAttribute(hgemm_kernel<false>,
                         cudaFuncAttributeMaxDynamicSharedMemorySize, GEMM_SMEM);

    // QKV = x @ W_qkv + b  -> fp16 hi (+ lo for Q columns only)
    hgemm_kernel<true><<<dim3(QKVN / 128, Mrows / 128), 256, GEMM_SMEM>>>(
        (const __half*)pxh, (const __half*)pxl, (const __half*)pwqh,
        bqkv, nullptr, (__half*)pqh, (__half*)pql, Mrows, QKVN, Dm, Dm);

    // attention (HMMA flash, 2-term)
    cudaFuncSetAttribute(flash_kernel,
                         cudaFuncAttributeMaxDynamicSharedMemorySize, FLASH_SMEM);
    flash_kernel<<<dim3(Sq / 128, Hh, Bsz), 256, FLASH_SMEM>>>(
        (const __half*)pqh, (const __half*)pql);

    // out = attn @ W_proj + b  -> f32
    hgemm_kernel<false><<<dim3(Dm / 128, Mrows / 128), 256, GEMM_SMEM>>>(
        (const __half*)pah, (const __half*)pal, (const __half*)pwph,
        bproj, out, nullptr, nullptr, Mrows, Dm, Dm, 0);
}